// round 5
// baseline (speedup 1.0000x reference)
#include <cuda_runtime.h>
#include <cuda_fp16.h>
#include <cuda_bf16.h>
#include <cstdint>

// ---------------------------------------------------------------------------
// Problem constants
// ---------------------------------------------------------------------------
#define VOCAB 10000
#define VPAD  10240          // 40 * 256
#define EMB   64
#define HID   128
#define BATCH 32
#define TLEN  256
#define ROWS  (BATCH * TLEN) // 8192

// ---------------------------------------------------------------------------
// Device scratch (no allocation allowed)
// ---------------------------------------------------------------------------
__device__ __align__(16) float   g_xw[ROWS * HID];       // 4 MB
__device__ __align__(16) __half  g_rnn_hi[ROWS * HID];   // 2 MB
__device__ __align__(16) __half  g_rnn_lo[ROWS * HID];   // 2 MB
__device__ __align__(16) __half  g_wdt_h[VPAD * HID];    // 2.6 MB
__device__ int g_ids_is64;

// ---------------------------------------------------------------------------
// PTX helpers (plain-target instructions only; no tcgen05)
// ---------------------------------------------------------------------------
__device__ __forceinline__ uint32_t smem_u32(const void* p) {
    uint32_t a;
    asm("{ .reg .u64 t; cvta.to.shared.u64 t, %1; cvt.u32.u64 %0, t; }" : "=r"(a) : "l"(p));
    return a;
}
__device__ __forceinline__ void ldsm_x4(uint32_t* r, uint32_t addr) {
    asm volatile("ldmatrix.sync.aligned.m8n8.x4.shared.b16 {%0,%1,%2,%3}, [%4];"
                 : "=r"(r[0]), "=r"(r[1]), "=r"(r[2]), "=r"(r[3]) : "r"(addr));
}
__device__ __forceinline__ void mma16816(float* c, const uint32_t* a,
                                         uint32_t b0, uint32_t b1) {
    asm volatile("mma.sync.aligned.m16n8k16.row.col.f32.f16.f16.f32 "
                 "{%0,%1,%2,%3}, {%4,%5,%6,%7}, {%8,%9}, {%0,%1,%2,%3};"
                 : "+f"(c[0]), "+f"(c[1]), "+f"(c[2]), "+f"(c[3])
                 : "r"(a[0]), "r"(a[1]), "r"(a[2]), "r"(a[3]), "r"(b0), "r"(b1));
}
__device__ __forceinline__ void cp16(uint32_t dst, const void* src) {
    asm volatile("cp.async.cg.shared.global [%0], [%1], 16;" :: "r"(dst), "l"(src));
}
#define CP_COMMIT()  asm volatile("cp.async.commit_group;" ::: "memory")
#define CP_WAIT(N)   asm volatile("cp.async.wait_group %0;" :: "n"(N) : "memory")

// packed f32x2 fma (Blackwell base; ptxas encodes FFMA2 only via this PTX)
__device__ __forceinline__ void fma2(unsigned long long& acc,
                                     unsigned long long a, unsigned long long b) {
    asm("fma.rn.f32x2 %0, %1, %2, %0;" : "+l"(acc) : "l"(a), "l"(b));
}
__device__ __forceinline__ unsigned long long pack2(float x, float y) {
    unsigned long long p;
    asm("mov.b64 %0, {%1, %2};" : "=l"(p) : "f"(x), "f"(y));
    return p;
}
__device__ __forceinline__ void unpack2(unsigned long long p, float& x, float& y) {
    asm("mov.b64 {%0, %1}, %2;" : "=f"(x), "=f"(y) : "l"(p));
}

// ---------------------------------------------------------------------------
// Kernel 0: detect inp_ids dtype (int64 vs int32) via odd 32-bit words
// ---------------------------------------------------------------------------
__global__ void k_detect(const unsigned int* __restrict__ w) {
    __shared__ int any;
    if (threadIdx.x == 0) any = 0;
    __syncthreads();
    unsigned int x = 0;
    for (int i = threadIdx.x; i < 2048; i += 256) x |= w[2 * i + 1];
    if (x) atomicOr(&any, 1);
    __syncthreads();
    if (threadIdx.x == 0) g_ids_is64 = any ? 0 : 1;
}

// ---------------------------------------------------------------------------
// Kernel 1: transpose Wd -> WdT[v][k] fp16, zero-padded to VPAD
// ---------------------------------------------------------------------------
__global__ void k_wdt(const float* __restrict__ Wd) {
    __shared__ float tile[32][33];
    int n0 = blockIdx.x * 32;   // vocab
    int k0 = blockIdx.y * 32;   // hid
    int tx = threadIdx.x, ty = threadIdx.y;  // 32 x 8
    #pragma unroll
    for (int i = 0; i < 32; i += 8) {
        int k = k0 + ty + i, n = n0 + tx;
        tile[ty + i][tx] = (n < VOCAB) ? Wd[(size_t)k * VOCAB + n] : 0.f;
    }
    __syncthreads();
    #pragma unroll
    for (int i = 0; i < 32; i += 8) {
        int n = n0 + ty + i, k = k0 + tx;
        g_wdt_h[n * HID + k] = __float2half(tile[tx][ty + i]);
    }
}

// ---------------------------------------------------------------------------
// Kernel 2: embedding lookup + input projection
// ---------------------------------------------------------------------------
__global__ void k_embed(const void* __restrict__ ids_raw,
                        const float* __restrict__ emb,
                        const float* __restrict__ W,
                        const float* __restrict__ b) {
    __shared__ float Ws[EMB * HID];
    __shared__ float xs[16][EMB];
    int j = threadIdx.x;
    int is64 = g_ids_is64;
    for (int i = j; i < EMB * HID; i += 128) Ws[i] = W[i];
    int r0 = blockIdx.x * 16;
    for (int p = j; p < 16 * EMB; p += 128) {
        int ri = p >> 6, e = p & 63;
        long long id = is64 ? ((const long long*)ids_raw)[r0 + ri]
                            : (long long)((const int*)ids_raw)[r0 + ri];
        xs[ri][e] = emb[id * EMB + e];
    }
    __syncthreads();
    float bj = b[j];
    #pragma unroll 1
    for (int ri = 0; ri < 16; ri++) {
        float a0 = bj, a1 = 0.f;
        #pragma unroll
        for (int e = 0; e < EMB; e += 2) {
            a0 += xs[ri][e]     * Ws[e * HID + j];
            a1 += xs[ri][e + 1] * Ws[(e + 1) * HID + j];
        }
        g_xw[(r0 + ri) * HID + j] = a0 + a1;
    }
}

// ---------------------------------------------------------------------------
// Kernel 3: RNN scan, 2 batches per CTA (warps 0-3 = batch A, 4-7 = batch B;
// the two recurrences interleave on each SMSP to hide latency). Thread owns
// one hid unit of one batch; U packed in 64 f32x2 regs; h ping-pongs in SMEM.
// fp16 hi/lo emission happens AFTER the barrier (off the critical path).
// ---------------------------------------------------------------------------
__global__ void __launch_bounds__(2 * HID, 1) k_scan(const float* __restrict__ U) {
    __shared__ __align__(16) float h[2][2][HID];   // [batch-in-cta][buf][unit]
    int bi = threadIdx.x >> 7;                     // 0/1: batch within CTA
    int j  = threadIdx.x & 127;                    // hid unit
    int bb = blockIdx.x * 2 + bi;

    unsigned long long u2[HID / 2];
    #pragma unroll
    for (int q = 0; q < HID / 2; q++)
        u2[q] = pack2(U[(2 * q) * HID + j], U[(2 * q + 1) * HID + j]);

    h[bi][0][j] = 0.f;
    __syncthreads();

    const float* xwp = g_xw + (size_t)bb * TLEN * HID + j;
    __half* outhi = g_rnn_hi + (size_t)bb * TLEN * HID + j;
    __half* outlo = g_rnn_lo + (size_t)bb * TLEN * HID + j;
    float xw_cur = xwp[0];
    int buf = 0;
    float h_prev = 0.f;     // value produced at step t-1, emitted after barrier
    int   emit   = 0;

    #pragma unroll 1
    for (int t = 0; t < TLEN; t++) {
        float xw_next = (t < TLEN - 1) ? xwp[(t + 1) * HID] : 0.f;

        unsigned long long a0 = pack2(xw_cur, 0.f), a1 = 0ull, a2 = 0ull, a3 = 0ull;
        const ulonglong2* hp = (const ulonglong2*)&h[bi][buf][0];
        #pragma unroll
        for (int i = 0; i < 32; i += 2) {
            ulonglong2 ha = hp[i];
            ulonglong2 hb = hp[i + 1];
            fma2(a0, u2[2 * i],     ha.x);
            fma2(a1, u2[2 * i + 1], ha.y);
            fma2(a2, u2[2 * i + 2], hb.x);
            fma2(a3, u2[2 * i + 3], hb.y);
        }
        float s0, s1, s2, s3, s4, s5, s6, s7;
        unpack2(a0, s0, s1); unpack2(a1, s2, s3);
        unpack2(a2, s4, s5); unpack2(a3, s6, s7);
        float z = ((s0 + s1) + (s2 + s3)) + ((s4 + s5) + (s6 + s7));

        float e = __expf(2.f * z);
        float hval = 1.f - __fdividef(2.f, e + 1.f);

        h[bi][buf ^ 1][j] = hval;          // STS first: only thing the barrier gates
        __syncthreads();

        // emit step t-1 (and later t=TLEN-1) off the critical path
        if (emit) {
            __half hi = __float2half(h_prev);
            outhi[(t - 1) * HID] = hi;
            outlo[(t - 1) * HID] = __float2half(h_prev - __half2float(hi));
        }
        h_prev = hval;
        emit = 1;
        buf ^= 1;
        xw_cur = xw_next;
    }
    {
        __half hi = __float2half(h_prev);
        outhi[(TLEN - 1) * HID] = hi;
        outlo[(TLEN - 1) * HID] = __float2half(h_prev - __half2float(hi));
    }
}

// ---------------------------------------------------------------------------
// Kernel 4: output GEMM, fp16 2-product (A=rnn hi/lo split, B=wdt fp16).
//   out[bt][v] = rnn[bt][k] @ WdT[v][k]^T + bd[v]
// CTA: v-tile 256 resident B (64 KB), 2 bt-tiles of 128, A double-buffered
// via cp.async (2 x 64 KB). 8 warps, warp tile 64x64.
// ---------------------------------------------------------------------------
#define SB_BYTES   65536                 // 256 x 256B (fp16)
#define SA_BYTES   65536                 // per buffer: hi 32K + lo 32K
#define SM_TOTAL   (SB_BYTES + 2 * SA_BYTES)   // 192 KB

__global__ void __launch_bounds__(256, 1) k_gemm(const float* __restrict__ bd,
                                                 float* __restrict__ out) {
    extern __shared__ char smem[];
    uint32_t sB = smem_u32(smem);
    uint32_t sA0 = sB + SB_BYTES;

    int tid  = threadIdx.x;
    int wid  = tid >> 5;
    int lane = tid & 31;
    int v0   = blockIdx.x * 256;
    int btg  = blockIdx.y * 256;        // 2 tiles of 128

    // ---- prologue: async-load B (resident) + A tile 0, then A tile 1 ----
    #pragma unroll
    for (int i = tid; i < 4096; i += 256) {       // B: 256 rows x 16 chunks
        int row = i >> 4, ch = i & 15;
        uint32_t dst = sB + row * 256 + ((ch ^ (row & 7)) << 4);
        cp16(dst, g_wdt_h + (size_t)(v0 + row) * HID + ch * 8);
    }
    #pragma unroll
    for (int i = tid; i < 4096; i += 256) {       // A0: hi/lo x 128 rows x 16
        int split = i >> 11, row = (i >> 4) & 127, ch = i & 15;
        const __half* src = split ? g_rnn_lo : g_rnn_hi;
        uint32_t dst = sA0 + split * 32768 + row * 256 + ((ch ^ (row & 7)) << 4);
        cp16(dst, src + (size_t)(btg + row) * HID + ch * 8);
    }
    CP_COMMIT();                                   // G0 = B + A0
    #pragma unroll
    for (int i = tid; i < 4096; i += 256) {       // A1
        int split = i >> 11, row = (i >> 4) & 127, ch = i & 15;
        const __half* src = split ? g_rnn_lo : g_rnn_hi;
        uint32_t dst = sA0 + SA_BYTES + split * 32768 + row * 256 + ((ch ^ (row & 7)) << 4);
        cp16(dst, src + (size_t)(btg + 128 + row) * HID + ch * 8);
    }
    CP_COMMIT();                                   // G1 = A1

    int wm = wid & 1;          // 2 warps over bt (64 each)
    int wn = wid >> 1;         // 4 warps over v  (64 each)
    int rA  = ((lane >> 3) & 1) * 8 + (lane & 7);
    int kcA = lane >> 4;
    int rB  = ((lane >> 4) & 1) * 8 + (lane & 7);
    int kcB = (lane >> 3) & 1;
    int lx  = lane & 7;

    #pragma unroll 1
    for (int it = 0; it < 2; it++) {
        if (it == 0) { CP_WAIT(1); } else { CP_WAIT(0); }
        __syncthreads();

        uint32_t sAb = sA0 + it * SA_BYTES;
        int bt0 = btg + it * 128;

        float c[4][8][4];
        #pragma unroll
        for (int mb = 0; mb < 4; mb++)
            #pragma unroll
            for (int nb = 0; nb < 8; nb++)
                #pragma unroll
                for (int q = 0; q < 4; q++) c[mb][nb][q] = 0.f;

        #pragma unroll 1
        for (int cmb = 0; cmb < 2; cmb++) {        // A_hi * B, A_lo * B
            uint32_t aBase = sAb + cmb * 32768 + (uint32_t)(wm * 64 + rA) * 256;
            uint32_t bBase = sB + (uint32_t)(wn * 64 + rB) * 256;
            #pragma unroll 1
            for (int ks = 0; ks < 8; ks++) {
                uint32_t a[4][4], b[4][4];
                int kA = (ks * 2 + kcA) ^ lx;
                int kB = (ks * 2 + kcB) ^ lx;
                #pragma unroll
                for (int mb = 0; mb < 4; mb++)
                    ldsm_x4(a[mb], aBase + (uint32_t)(mb * 16) * 256 + (kA << 4));
                #pragma unroll
                for (int nb = 0; nb < 4; nb++)
                    ldsm_x4(b[nb], bBase + (uint32_t)(nb * 16) * 256 + (kB << 4));
                #pragma unroll
                for (int mb = 0; mb < 4; mb++)
                    #pragma unroll
                    for (int nbi = 0; nbi < 8; nbi++)
                        mma16816(c[mb][nbi], a[mb],
                                 b[nbi >> 1][(nbi & 1) * 2],
                                 b[nbi >> 1][(nbi & 1) * 2 + 1]);
            }
        }

        // ---- epilogue: bias + store ----
        #pragma unroll
        for (int nbi = 0; nbi < 8; nbi++) {
            int col = v0 + wn * 64 + nbi * 8 + (lane & 3) * 2;
            if (col < VOCAB) {
                float b0 = bd[col], b1 = bd[col + 1];
                #pragma unroll
                for (int mb = 0; mb < 4; mb++) {
                    int r = bt0 + wm * 64 + mb * 16 + (lane >> 2);
                    float2 lo = make_float2(c[mb][nbi][0] + b0, c[mb][nbi][1] + b1);
                    float2 hi = make_float2(c[mb][nbi][2] + b0, c[mb][nbi][3] + b1);
                    *(float2*)(out + (size_t)r * VOCAB + col) = lo;
                    *(float2*)(out + (size_t)(r + 8) * VOCAB + col) = hi;
                }
            }
        }
        __syncthreads();
    }
}

// ---------------------------------------------------------------------------
// Launch: fork k_wdt onto a side stream (captured via events), join for gemm
// ---------------------------------------------------------------------------
extern "C" void kernel_launch(void* const* d_in, const int* in_sizes, int n_in,
                              void* d_out, int out_size) {
    const void*  ids = d_in[0];
    const float* emb = (const float*)d_in[1];
    const float* W   = (const float*)d_in[2];
    const float* U   = (const float*)d_in[3];
    const float* b   = (const float*)d_in[4];
    const float* Wd  = (const float*)d_in[5];
    const float* bd  = (const float*)d_in[6];
    float* out = (float*)d_out;

    static cudaStream_t s2 = nullptr;
    static cudaEvent_t eFork = nullptr, eJoin = nullptr;
    if (!s2) {
        cudaStreamCreateWithFlags(&s2, cudaStreamNonBlocking);
        cudaEventCreateWithFlags(&eFork, cudaEventDisableTiming);
        cudaEventCreateWithFlags(&eJoin, cudaEventDisableTiming);
        cudaFuncSetAttribute(k_gemm, cudaFuncAttributeMaxDynamicSharedMemorySize, SM_TOTAL);
    }

    cudaEventRecord(eFork, 0);
    cudaStreamWaitEvent(s2, eFork, 0);
    k_wdt<<<dim3(VPAD / 32, HID / 32), dim3(32, 8), 0, s2>>>(Wd);
    cudaEventRecord(eJoin, s2);

    k_detect<<<1, 256>>>((const unsigned int*)ids);
    k_embed<<<ROWS / 16, 128>>>(ids, emb, W, b);
    k_scan<<<BATCH / 2, 2 * HID>>>(U);

    cudaStreamWaitEvent(0, eJoin, 0);
    k_gemm<<<dim3(VPAD / 256, ROWS / 256), 256, SM_TOTAL>>>(bd, out);
}

// round 7
// speedup vs baseline: 1.1440x; 1.1440x over previous
#include <cuda_runtime.h>
#include <cuda_fp16.h>
#include <cstdint>

// ---------------------------------------------------------------------------
// Problem constants
// ---------------------------------------------------------------------------
#define VOCAB 10000
#define VPAD  10240          // 40 * 256
#define EMB   64
#define HID   128
#define BATCH 32
#define TLEN  256
#define ROWS  (BATCH * TLEN) // 8192

// ---------------------------------------------------------------------------
// Device scratch (no allocation allowed)
// ---------------------------------------------------------------------------
__device__ __align__(16) float   g_xw[ROWS * HID];       // 4 MB
__device__ __align__(16) __half  g_rnn_h[ROWS * HID];    // 2 MB
__device__ __align__(16) __half  g_wdt_h[VPAD * HID];    // 2.6 MB
__device__ int g_ids_is64;

// ---------------------------------------------------------------------------
// PTX helpers (plain-target instructions only; no tcgen05)
// ---------------------------------------------------------------------------
__device__ __forceinline__ uint32_t smem_u32(const void* p) {
    uint32_t a;
    asm("{ .reg .u64 t; cvta.to.shared.u64 t, %1; cvt.u32.u64 %0, t; }" : "=r"(a) : "l"(p));
    return a;
}
__device__ __forceinline__ void ldsm_x4(uint32_t* r, uint32_t addr) {
    asm volatile("ldmatrix.sync.aligned.m8n8.x4.shared.b16 {%0,%1,%2,%3}, [%4];"
                 : "=r"(r[0]), "=r"(r[1]), "=r"(r[2]), "=r"(r[3]) : "r"(addr));
}
__device__ __forceinline__ void mma16816(float* c, const uint32_t* a,
                                         uint32_t b0, uint32_t b1) {
    asm volatile("mma.sync.aligned.m16n8k16.row.col.f32.f16.f16.f32 "
                 "{%0,%1,%2,%3}, {%4,%5,%6,%7}, {%8,%9}, {%0,%1,%2,%3};"
                 : "+f"(c[0]), "+f"(c[1]), "+f"(c[2]), "+f"(c[3])
                 : "r"(a[0]), "r"(a[1]), "r"(a[2]), "r"(a[3]), "r"(b0), "r"(b1));
}
__device__ __forceinline__ void cp16(uint32_t dst, const void* src) {
    asm volatile("cp.async.cg.shared.global [%0], [%1], 16;" :: "r"(dst), "l"(src));
}
#define CP_COMMIT()  asm volatile("cp.async.commit_group;" ::: "memory")
#define CP_WAIT(N)   asm volatile("cp.async.wait_group %0;" :: "n"(N) : "memory")

// packed f32x2 ops
__device__ __forceinline__ void fma2(unsigned long long& acc,
                                     unsigned long long a, unsigned long long b) {
    asm("fma.rn.f32x2 %0, %1, %2, %0;" : "+l"(acc) : "l"(a), "l"(b));
}
__device__ __forceinline__ unsigned long long add2(unsigned long long a,
                                                   unsigned long long b) {
    unsigned long long d;
    asm("add.rn.f32x2 %0, %1, %2;" : "=l"(d) : "l"(a), "l"(b));
    return d;
}
__device__ __forceinline__ unsigned long long pack2(float x, float y) {
    unsigned long long p;
    asm("mov.b64 %0, {%1, %2};" : "=l"(p) : "f"(x), "f"(y));
    return p;
}
__device__ __forceinline__ void unpack2(unsigned long long p, float& x, float& y) {
    asm("mov.b64 {%0, %1}, %2;" : "=f"(x), "=f"(y) : "l"(p));
}

// ---------------------------------------------------------------------------
// Kernel 0: detect inp_ids dtype (int64 vs int32) via odd 32-bit words
// ---------------------------------------------------------------------------
__global__ void k_detect(const unsigned int* __restrict__ w) {
    __shared__ int any;
    if (threadIdx.x == 0) any = 0;
    __syncthreads();
    unsigned int x = 0;
    for (int i = threadIdx.x; i < 2048; i += 256) x |= w[2 * i + 1];
    if (x) atomicOr(&any, 1);
    __syncthreads();
    if (threadIdx.x == 0) g_ids_is64 = any ? 0 : 1;
}

// ---------------------------------------------------------------------------
// Kernel 1: transpose Wd -> WdT[v][k] fp16, zero-padded to VPAD
// ---------------------------------------------------------------------------
__global__ void k_wdt(const float* __restrict__ Wd) {
    __shared__ float tile[32][33];
    int n0 = blockIdx.x * 32;   // vocab
    int k0 = blockIdx.y * 32;   // hid
    int tx = threadIdx.x, ty = threadIdx.y;  // 32 x 8
    #pragma unroll
    for (int i = 0; i < 32; i += 8) {
        int k = k0 + ty + i, n = n0 + tx;
        tile[ty + i][tx] = (n < VOCAB) ? Wd[(size_t)k * VOCAB + n] : 0.f;
    }
    __syncthreads();
    #pragma unroll
    for (int i = 0; i < 32; i += 8) {
        int n = n0 + ty + i, k = k0 + tx;
        g_wdt_h[n * HID + k] = __float2half(tile[tx][ty + i]);
    }
}

// ---------------------------------------------------------------------------
// Kernel 2: embedding lookup + input projection
// ---------------------------------------------------------------------------
__global__ void k_embed(const void* __restrict__ ids_raw,
                        const float* __restrict__ emb,
                        const float* __restrict__ W,
                        const float* __restrict__ b) {
    __shared__ float Ws[EMB * HID];
    __shared__ float xs[16][EMB];
    int j = threadIdx.x;
    int is64 = g_ids_is64;
    for (int i = j; i < EMB * HID; i += 128) Ws[i] = W[i];
    int r0 = blockIdx.x * 16;
    for (int p = j; p < 16 * EMB; p += 128) {
        int ri = p >> 6, e = p & 63;
        long long id = is64 ? ((const long long*)ids_raw)[r0 + ri]
                            : (long long)((const int*)ids_raw)[r0 + ri];
        xs[ri][e] = emb[id * EMB + e];
    }
    __syncthreads();
    float bj = b[j];
    #pragma unroll 1
    for (int ri = 0; ri < 16; ri++) {
        float a0 = bj, a1 = 0.f;
        #pragma unroll
        for (int e = 0; e < EMB; e += 2) {
            a0 += xs[ri][e]     * Ws[e * HID + j];
            a1 += xs[ri][e + 1] * Ws[(e + 1) * HID + j];
        }
        g_xw[(r0 + ri) * HID + j] = a0 + a1;
    }
}

// ---------------------------------------------------------------------------
// Kernel 3: RNN scan (round-4 shape: 1 batch/CTA, 128 thr). 8 independent
// f32x2 accumulator chains (depth 8); f32x2 reduction tree; single fp16
// emission moved after the barrier (off the critical path).
// ---------------------------------------------------------------------------
__global__ void __launch_bounds__(HID, 1) k_scan(const float* __restrict__ U) {
    __shared__ __align__(16) float h[2][HID];
    int bb = blockIdx.x;
    int j  = threadIdx.x;

    unsigned long long u2[HID / 2];
    #pragma unroll
    for (int q = 0; q < HID / 2; q++)
        u2[q] = pack2(U[(2 * q) * HID + j], U[(2 * q + 1) * HID + j]);

    h[0][j] = 0.f;
    __syncthreads();

    const float* xwp  = g_xw   + (size_t)bb * TLEN * HID + j;
    __half*      outp = g_rnn_h + (size_t)bb * TLEN * HID + j;
    float xw_cur = xwp[0];
    int buf = 0;
    float h_prev = 0.f;
    int   emit   = 0;

    #pragma unroll 1
    for (int t = 0; t < TLEN; t++) {
        float xw_next = (t < TLEN - 1) ? xwp[(t + 1) * HID] : 0.f;

        unsigned long long a[8];
        a[0] = pack2(xw_cur, 0.f);
        #pragma unroll
        for (int q = 1; q < 8; q++) a[q] = 0ull;

        const ulonglong2* hp = (const ulonglong2*)&h[buf][0];
        #pragma unroll
        for (int i = 0; i < 32; i++) {
            ulonglong2 hv = hp[i];
            fma2(a[(2 * i) & 7],     u2[2 * i],     hv.x);
            fma2(a[(2 * i + 1) & 7], u2[2 * i + 1], hv.y);
        }
        unsigned long long r0 = add2(a[0], a[1]);
        unsigned long long r1 = add2(a[2], a[3]);
        unsigned long long r2 = add2(a[4], a[5]);
        unsigned long long r3 = add2(a[6], a[7]);
        unsigned long long s  = add2(add2(r0, r1), add2(r2, r3));
        float zx, zy;
        unpack2(s, zx, zy);
        float z = zx + zy;

        float e = __expf(2.f * z);
        float hval = 1.f - __fdividef(2.f, e + 1.f);

        h[buf ^ 1][j] = hval;              // STS first: only thing the barrier gates
        __syncthreads();

        if (emit) outp[(t - 1) * HID] = __float2half(h_prev);
        h_prev = hval;
        emit = 1;
        buf ^= 1;
        xw_cur = xw_next;
    }
    outp[(TLEN - 1) * HID] = __float2half(h_prev);
}

// ---------------------------------------------------------------------------
// Kernel 4: output GEMM, single fp16 product (A=rnn fp16, B=wdt fp16).
//   out[bt][v] = rnn[bt][k] @ WdT[v][k]^T + bd[v]
// CTA: v-tile 256 resident B (64 KB); 8 bt-tiles of 128 streamed through a
// 3-stage cp.async pipeline (3 x 32 KB). 8 warps, warp tile 64x64.
// ---------------------------------------------------------------------------
#define SB_BYTES   65536                 // 256 rows x 256B (fp16)
#define SA_BYTES   32768                 // per stage: 128 rows x 256B
#define N_STAGE    3
#define N_TILES    8
#define SM_TOTAL   (SB_BYTES + N_STAGE * SA_BYTES)   // 160 KB

__device__ __forceinline__ void gemm_load_a(uint32_t sAbuf, int bt0, int tid) {
    #pragma unroll
    for (int i = tid; i < 2048; i += 256) {       // 128 rows x 16 chunks
        int row = i >> 4, ch = i & 15;
        uint32_t dst = sAbuf + row * 256 + ((ch ^ (row & 7)) << 4);
        cp16(dst, g_rnn_h + (size_t)(bt0 + row) * HID + ch * 8);
    }
}

__global__ void __launch_bounds__(256, 1) k_gemm(const float* __restrict__ bd,
                                                 float* __restrict__ out) {
    extern __shared__ char smem[];
    uint32_t sB  = smem_u32(smem);
    uint32_t sA0 = sB + SB_BYTES;

    int tid  = threadIdx.x;
    int wid  = tid >> 5;
    int lane = tid & 31;
    int v0   = blockIdx.x * 256;
    int btg  = blockIdx.y * (N_TILES * 128);

    // ---- prologue: B (resident) + A0 in group 0; A1, A2 in groups 1, 2 ----
    #pragma unroll
    for (int i = tid; i < 4096; i += 256) {       // B: 256 rows x 16 chunks
        int row = i >> 4, ch = i & 15;
        uint32_t dst = sB + row * 256 + ((ch ^ (row & 7)) << 4);
        cp16(dst, g_wdt_h + (size_t)(v0 + row) * HID + ch * 8);
    }
    gemm_load_a(sA0, btg, tid);
    CP_COMMIT();
    gemm_load_a(sA0 + SA_BYTES, btg + 128, tid);
    CP_COMMIT();
    gemm_load_a(sA0 + 2 * SA_BYTES, btg + 256, tid);
    CP_COMMIT();

    int wm = wid & 1;          // 2 warps over bt (64 each)
    int wn = wid >> 1;         // 4 warps over v  (64 each)
    int rA  = ((lane >> 3) & 1) * 8 + (lane & 7);
    int kcA = lane >> 4;
    int rB  = ((lane >> 4) & 1) * 8 + (lane & 7);
    int kcB = (lane >> 3) & 1;
    int lx  = lane & 7;

    #pragma unroll 1
    for (int it = 0; it < N_TILES; it++) {
        CP_WAIT(2);                                // A_it (and B for it=0) done
        __syncthreads();

        uint32_t sAb = sA0 + (it % N_STAGE) * SA_BYTES;
        int bt0 = btg + it * 128;

        float c[4][8][4];
        #pragma unroll
        for (int mb = 0; mb < 4; mb++)
            #pragma unroll
            for (int nb = 0; nb < 8; nb++)
                #pragma unroll
                for (int q = 0; q < 4; q++) c[mb][nb][q] = 0.f;

        uint32_t aBase = sAb + (uint32_t)(wm * 64 + rA) * 256;
        uint32_t bBase = sB  + (uint32_t)(wn * 64 + rB) * 256;
        #pragma unroll 1
        for (int ks = 0; ks < 8; ks++) {
            uint32_t a[4][4], b[4][4];
            int kA = (ks * 2 + kcA) ^ lx;
            int kB = (ks * 2 + kcB) ^ lx;
            #pragma unroll
            for (int mb = 0; mb < 4; mb++)
                ldsm_x4(a[mb], aBase + (uint32_t)(mb * 16) * 256 + (kA << 4));
            #pragma unroll
            for (int nb = 0; nb < 4; nb++)
                ldsm_x4(b[nb], bBase + (uint32_t)(nb * 16) * 256 + (kB << 4));
            #pragma unroll
            for (int mb = 0; mb < 4; mb++)
                #pragma unroll
                for (int nbi = 0; nbi < 8; nbi++)
                    mma16816(c[mb][nbi], a[mb],
                             b[nbi >> 1][(nbi & 1) * 2],
                             b[nbi >> 1][(nbi & 1) * 2 + 1]);
        }

        __syncthreads();                           // A_it consumed; stage reusable
        if (it + N_STAGE < N_TILES) {
            gemm_load_a(sA0 + (it % N_STAGE) * SA_BYTES, btg + (it + N_STAGE) * 128, tid);
        }
        CP_COMMIT();                               // keep group count in lockstep

        // ---- epilogue: bias + store (overlaps in-flight cp.async) ----
        #pragma unroll
        for (int nbi = 0; nbi < 8; nbi++) {
            int col = v0 + wn * 64 + nbi * 8 + (lane & 3) * 2;
            if (col < VOCAB) {
                float b0 = bd[col], b1 = bd[col + 1];
                #pragma unroll
                for (int mb = 0; mb < 4; mb++) {
                    int r = bt0 + wm * 64 + mb * 16 + (lane >> 2);
                    float2 lo = make_float2(c[mb][nbi][0] + b0, c[mb][nbi][1] + b1);
                    float2 hi = make_float2(c[mb][nbi][2] + b0, c[mb][nbi][3] + b1);
                    *(float2*)(out + (size_t)r * VOCAB + col) = lo;
                    *(float2*)(out + (size_t)(r + 8) * VOCAB + col) = hi;
                }
            }
        }
    }
}

// ---------------------------------------------------------------------------
// Launch: fork k_wdt onto a side stream (captured via events), join for gemm
// ---------------------------------------------------------------------------
extern "C" void kernel_launch(void* const* d_in, const int* in_sizes, int n_in,
                              void* d_out, int out_size) {
    const void*  ids = d_in[0];
    const float* emb = (const float*)d_in[1];
    const float* W   = (const float*)d_in[2];
    const float* U   = (const float*)d_in[3];
    const float* b   = (const float*)d_in[4];
    const float* Wd  = (const float*)d_in[5];
    const float* bd  = (const float*)d_in[6];
    float* out = (float*)d_out;

    static cudaStream_t s2 = nullptr;
    static cudaEvent_t eFork = nullptr, eJoin = nullptr;
    if (!s2) {
        cudaStreamCreateWithFlags(&s2, cudaStreamNonBlocking);
        cudaEventCreateWithFlags(&eFork, cudaEventDisableTiming);
        cudaEventCreateWithFlags(&eJoin, cudaEventDisableTiming);
        cudaFuncSetAttribute(k_gemm, cudaFuncAttributeMaxDynamicSharedMemorySize, SM_TOTAL);
    }

    cudaEventRecord(eFork, 0);
    cudaStreamWaitEvent(s2, eFork, 0);
    k_wdt<<<dim3(VPAD / 32, HID / 32), dim3(32, 8), 0, s2>>>(Wd);
    cudaEventRecord(eJoin, s2);

    k_detect<<<1, 256>>>((const unsigned int*)ids);
    k_embed<<<ROWS / 16, 128>>>(ids, emb, W, b);
    k_scan<<<BATCH, HID>>>(U);

    cudaStreamWaitEvent(0, eJoin, 0);
    k_gemm<<<dim3(VPAD / 256, ROWS / (N_TILES * 128)), 256, SM_TOTAL>>>(bd, out);
}

// round 8
// speedup vs baseline: 1.3550x; 1.1844x over previous
#include <cuda_runtime.h>
#include <cuda_fp16.h>
#include <cstdint>

// ---------------------------------------------------------------------------
// Problem constants
// ---------------------------------------------------------------------------
#define VOCAB 10000
#define VPAD  10240          // 40 * 256
#define EMB   64
#define HID   128
#define BATCH 32
#define TLEN  256
#define TCH   128            // timestep chunk (2 chunks)
#define ROWS  (BATCH * TLEN) // 8192

// ---------------------------------------------------------------------------
// Device scratch (no allocation allowed)
// ---------------------------------------------------------------------------
__device__ __align__(16) float   g_xw[ROWS * HID];       // 4 MB
__device__ __align__(16) __half  g_rnn_h[ROWS * HID];    // 2 MB
__device__ __align__(16) __half  g_wdt_h[VPAD * HID];    // 2.6 MB
__device__ __align__(16) float   g_hst[BATCH * HID];     // scan state hand-off
__device__ int g_ids_is64;

// ---------------------------------------------------------------------------
// PTX helpers (plain-target instructions only; no tcgen05)
// ---------------------------------------------------------------------------
__device__ __forceinline__ uint32_t smem_u32(const void* p) {
    uint32_t a;
    asm("{ .reg .u64 t; cvta.to.shared.u64 t, %1; cvt.u32.u64 %0, t; }" : "=r"(a) : "l"(p));
    return a;
}
__device__ __forceinline__ void ldsm_x4(uint32_t* r, uint32_t addr) {
    asm volatile("ldmatrix.sync.aligned.m8n8.x4.shared.b16 {%0,%1,%2,%3}, [%4];"
                 : "=r"(r[0]), "=r"(r[1]), "=r"(r[2]), "=r"(r[3]) : "r"(addr));
}
__device__ __forceinline__ void mma16816(float* c, const uint32_t* a,
                                         uint32_t b0, uint32_t b1) {
    asm volatile("mma.sync.aligned.m16n8k16.row.col.f32.f16.f16.f32 "
                 "{%0,%1,%2,%3}, {%4,%5,%6,%7}, {%8,%9}, {%0,%1,%2,%3};"
                 : "+f"(c[0]), "+f"(c[1]), "+f"(c[2]), "+f"(c[3])
                 : "r"(a[0]), "r"(a[1]), "r"(a[2]), "r"(a[3]), "r"(b0), "r"(b1));
}
__device__ __forceinline__ void cp16(uint32_t dst, const void* src) {
    asm volatile("cp.async.cg.shared.global [%0], [%1], 16;" :: "r"(dst), "l"(src));
}
#define CP_COMMIT()  asm volatile("cp.async.commit_group;" ::: "memory")
#define CP_WAIT(N)   asm volatile("cp.async.wait_group %0;" :: "n"(N) : "memory")

// packed f32x2 ops
__device__ __forceinline__ void fma2(unsigned long long& acc,
                                     unsigned long long a, unsigned long long b) {
    asm("fma.rn.f32x2 %0, %1, %2, %0;" : "+l"(acc) : "l"(a), "l"(b));
}
__device__ __forceinline__ unsigned long long add2(unsigned long long a,
                                                   unsigned long long b) {
    unsigned long long d;
    asm("add.rn.f32x2 %0, %1, %2;" : "=l"(d) : "l"(a), "l"(b));
    return d;
}
__device__ __forceinline__ unsigned long long pack2(float x, float y) {
    unsigned long long p;
    asm("mov.b64 %0, {%1, %2};" : "=l"(p) : "f"(x), "f"(y));
    return p;
}
__device__ __forceinline__ void unpack2(unsigned long long p, float& x, float& y) {
    asm("mov.b64 {%0, %1}, %2;" : "=f"(x), "=f"(y) : "l"(p));
}

// ---------------------------------------------------------------------------
// Kernel 0: detect inp_ids dtype (int64 vs int32) via odd 32-bit words
// ---------------------------------------------------------------------------
__global__ void k_detect(const unsigned int* __restrict__ w) {
    __shared__ int any;
    if (threadIdx.x == 0) any = 0;
    __syncthreads();
    unsigned int x = 0;
    for (int i = threadIdx.x; i < 2048; i += 256) x |= w[2 * i + 1];
    if (x) atomicOr(&any, 1);
    __syncthreads();
    if (threadIdx.x == 0) g_ids_is64 = any ? 0 : 1;
}

// ---------------------------------------------------------------------------
// Kernel 1: transpose Wd -> WdT[v][k] fp16, zero-padded to VPAD
// ---------------------------------------------------------------------------
__global__ void k_wdt(const float* __restrict__ Wd) {
    __shared__ float tile[32][33];
    int n0 = blockIdx.x * 32;   // vocab
    int k0 = blockIdx.y * 32;   // hid
    int tx = threadIdx.x, ty = threadIdx.y;  // 32 x 8
    #pragma unroll
    for (int i = 0; i < 32; i += 8) {
        int k = k0 + ty + i, n = n0 + tx;
        tile[ty + i][tx] = (n < VOCAB) ? Wd[(size_t)k * VOCAB + n] : 0.f;
    }
    __syncthreads();
    #pragma unroll
    for (int i = 0; i < 32; i += 8) {
        int n = n0 + ty + i, k = k0 + tx;
        g_wdt_h[n * HID + k] = __float2half(tile[tx][ty + i]);
    }
}

// ---------------------------------------------------------------------------
// Kernel 2: embedding lookup + input projection
// ---------------------------------------------------------------------------
__global__ void k_embed(const void* __restrict__ ids_raw,
                        const float* __restrict__ emb,
                        const float* __restrict__ W,
                        const float* __restrict__ b) {
    __shared__ float Ws[EMB * HID];
    __shared__ float xs[16][EMB];
    int j = threadIdx.x;
    int is64 = g_ids_is64;
    for (int i = j; i < EMB * HID; i += 128) Ws[i] = W[i];
    int r0 = blockIdx.x * 16;
    for (int p = j; p < 16 * EMB; p += 128) {
        int ri = p >> 6, e = p & 63;
        long long id = is64 ? ((const long long*)ids_raw)[r0 + ri]
                            : (long long)((const int*)ids_raw)[r0 + ri];
        xs[ri][e] = emb[id * EMB + e];
    }
    __syncthreads();
    float bj = b[j];
    #pragma unroll 1
    for (int ri = 0; ri < 16; ri++) {
        float a0 = bj, a1 = 0.f;
        #pragma unroll
        for (int e = 0; e < EMB; e += 2) {
            a0 += xs[ri][e]     * Ws[e * HID + j];
            a1 += xs[ri][e + 1] * Ws[(e + 1) * HID + j];
        }
        g_xw[(r0 + ri) * HID + j] = a0 + a1;
    }
}

// ---------------------------------------------------------------------------
// Kernel 3: RNN scan CHUNK of TCH steps. 1 batch/CTA, 128 thr. State is
// carried through g_hst (fp32, exact) so chunk 2 continues bit-identically.
// fp16 emission happens after the barrier (off the critical path).
// ---------------------------------------------------------------------------
__global__ void __launch_bounds__(HID, 1) k_scan(const float* __restrict__ U, int t0) {
    __shared__ __align__(16) float h[2][HID];
    int bb = blockIdx.x;
    int j  = threadIdx.x;

    unsigned long long u2[HID / 2];
    #pragma unroll
    for (int q = 0; q < HID / 2; q++)
        u2[q] = pack2(U[(2 * q) * HID + j], U[(2 * q + 1) * HID + j]);

    float h0 = (t0 == 0) ? 0.f : g_hst[bb * HID + j];
    h[0][j] = h0;
    __syncthreads();

    const float* xwp  = g_xw    + ((size_t)bb * TLEN + t0) * HID + j;
    __half*      outp = g_rnn_h + ((size_t)bb * TLEN + t0) * HID + j;
    float xw_cur = xwp[0];
    int buf = 0;
    float h_prev = 0.f;
    int   emit   = 0;

    #pragma unroll 1
    for (int t = 0; t < TCH; t++) {
        float xw_next = (t < TCH - 1) ? xwp[(t + 1) * HID] : 0.f;

        unsigned long long a[8];
        a[0] = pack2(xw_cur, 0.f);
        #pragma unroll
        for (int q = 1; q < 8; q++) a[q] = 0ull;

        const ulonglong2* hp = (const ulonglong2*)&h[buf][0];
        #pragma unroll
        for (int i = 0; i < 32; i++) {
            ulonglong2 hv = hp[i];
            fma2(a[(2 * i) & 7],     u2[2 * i],     hv.x);
            fma2(a[(2 * i + 1) & 7], u2[2 * i + 1], hv.y);
        }
        unsigned long long r0 = add2(a[0], a[1]);
        unsigned long long r1 = add2(a[2], a[3]);
        unsigned long long r2 = add2(a[4], a[5]);
        unsigned long long r3 = add2(a[6], a[7]);
        unsigned long long s  = add2(add2(r0, r1), add2(r2, r3));
        float zx, zy;
        unpack2(s, zx, zy);
        float z = zx + zy;

        float e = __expf(2.f * z);
        float hval = 1.f - __fdividef(2.f, e + 1.f);

        h[buf ^ 1][j] = hval;              // STS first: only thing the barrier gates
        __syncthreads();

        if (emit) outp[(t - 1) * HID] = __float2half(h_prev);
        h_prev = hval;
        emit = 1;
        buf ^= 1;
        xw_cur = xw_next;
    }
    outp[(TCH - 1) * HID] = __float2half(h_prev);
    g_hst[bb * HID + j] = h_prev;          // state hand-off (exact fp32)
}

// ---------------------------------------------------------------------------
// Kernel 4: output GEMM chunk, single fp16 product.
//   out[bt][v] = rnn[bt][k] @ WdT[v][k]^T + bd[v]   for t in [t0, t0+128)
// Grid (40, 8): CTA owns v-tile 256 (B resident 64 KB) and 4 batches'
// 128-row segments, streamed through a 3-stage cp.async pipeline.
// ---------------------------------------------------------------------------
#define SB_BYTES   65536                 // 256 rows x 256B (fp16)
#define SA_BYTES   32768                 // per stage: 128 rows x 256B
#define N_STAGE    3
#define N_TILES    4
#define SM_TOTAL   (SB_BYTES + N_STAGE * SA_BYTES)   // 160 KB

__device__ __forceinline__ void gemm_load_a(uint32_t sAbuf, int row0, int tid) {
    #pragma unroll
    for (int i = tid; i < 2048; i += 256) {       // 128 rows x 16 chunks
        int row = i >> 4, ch = i & 15;
        uint32_t dst = sAbuf + row * 256 + ((ch ^ (row & 7)) << 4);
        cp16(dst, g_rnn_h + (size_t)(row0 + row) * HID + ch * 8);
    }
}

__global__ void __launch_bounds__(256, 1) k_gemm(const float* __restrict__ bd,
                                                 float* __restrict__ out, int t0) {
    extern __shared__ char smem[];
    uint32_t sB  = smem_u32(smem);
    uint32_t sA0 = sB + SB_BYTES;

    int tid  = threadIdx.x;
    int wid  = tid >> 5;
    int lane = tid & 31;
    int v0   = blockIdx.x * 256;
    int bg   = blockIdx.y * 4;          // first batch of this CTA's 4

    // ---- prologue: B (resident) + A0 in group 0; A1, A2 in groups 1, 2 ----
    #pragma unroll
    for (int i = tid; i < 4096; i += 256) {       // B: 256 rows x 16 chunks
        int row = i >> 4, ch = i & 15;
        uint32_t dst = sB + row * 256 + ((ch ^ (row & 7)) << 4);
        cp16(dst, g_wdt_h + (size_t)(v0 + row) * HID + ch * 8);
    }
    gemm_load_a(sA0,                bg * TLEN + t0, tid);
    CP_COMMIT();
    gemm_load_a(sA0 + SA_BYTES,     (bg + 1) * TLEN + t0, tid);
    CP_COMMIT();
    gemm_load_a(sA0 + 2 * SA_BYTES, (bg + 2) * TLEN + t0, tid);
    CP_COMMIT();

    int wm = wid & 1;          // 2 warps over bt (64 each)
    int wn = wid >> 1;         // 4 warps over v  (64 each)
    int rA  = ((lane >> 3) & 1) * 8 + (lane & 7);
    int kcA = lane >> 4;
    int rB  = ((lane >> 4) & 1) * 8 + (lane & 7);
    int kcB = (lane >> 3) & 1;
    int lx  = lane & 7;

    #pragma unroll 1
    for (int it = 0; it < N_TILES; it++) {
        CP_WAIT(2);                                // A_it (and B for it=0) done
        __syncthreads();

        uint32_t sAb = sA0 + (it % N_STAGE) * SA_BYTES;
        int bt0 = (bg + it) * TLEN + t0;

        float c[4][8][4];
        #pragma unroll
        for (int mb = 0; mb < 4; mb++)
            #pragma unroll
            for (int nb = 0; nb < 8; nb++)
                #pragma unroll
                for (int q = 0; q < 4; q++) c[mb][nb][q] = 0.f;

        uint32_t aBase = sAb + (uint32_t)(wm * 64 + rA) * 256;
        uint32_t bBase = sB  + (uint32_t)(wn * 64 + rB) * 256;
        #pragma unroll 1
        for (int ks = 0; ks < 8; ks++) {
            uint32_t a[4][4], b[4][4];
            int kA = (ks * 2 + kcA) ^ lx;
            int kB = (ks * 2 + kcB) ^ lx;
            #pragma unroll
            for (int mb = 0; mb < 4; mb++)
                ldsm_x4(a[mb], aBase + (uint32_t)(mb * 16) * 256 + (kA << 4));
            #pragma unroll
            for (int nb = 0; nb < 4; nb++)
                ldsm_x4(b[nb], bBase + (uint32_t)(nb * 16) * 256 + (kB << 4));
            #pragma unroll
            for (int mb = 0; mb < 4; mb++)
                #pragma unroll
                for (int nbi = 0; nbi < 8; nbi++)
                    mma16816(c[mb][nbi], a[mb],
                             b[nbi >> 1][(nbi & 1) * 2],
                             b[nbi >> 1][(nbi & 1) * 2 + 1]);
        }

        __syncthreads();                           // A_it consumed; stage reusable
        if (it + N_STAGE < N_TILES) {
            gemm_load_a(sA0 + (it % N_STAGE) * SA_BYTES,
                        (bg + it + N_STAGE) * TLEN + t0, tid);
        }
        CP_COMMIT();                               // keep group count in lockstep

        // ---- epilogue: bias + store (overlaps in-flight cp.async) ----
        #pragma unroll
        for (int nbi = 0; nbi < 8; nbi++) {
            int col = v0 + wn * 64 + nbi * 8 + (lane & 3) * 2;
            if (col < VOCAB) {
                float b0 = bd[col], b1 = bd[col + 1];
                #pragma unroll
                for (int mb = 0; mb < 4; mb++) {
                    int r = bt0 + wm * 64 + mb * 16 + (lane >> 2);
                    float2 lo = make_float2(c[mb][nbi][0] + b0, c[mb][nbi][1] + b1);
                    float2 hi = make_float2(c[mb][nbi][2] + b0, c[mb][nbi][3] + b1);
                    *(float2*)(out + (size_t)r * VOCAB + col) = lo;
                    *(float2*)(out + (size_t)(r + 8) * VOCAB + col) = hi;
                }
            }
        }
    }
}

// ---------------------------------------------------------------------------
// Launch: wdt forked on s2; scan chunks on main stream; gemm chunks on s3
// overlapping scan chunk 2 with gemm chunk 1. Final join back to main.
// ---------------------------------------------------------------------------
extern "C" void kernel_launch(void* const* d_in, const int* in_sizes, int n_in,
                              void* d_out, int out_size) {
    const void*  ids = d_in[0];
    const float* emb = (const float*)d_in[1];
    const float* W   = (const float*)d_in[2];
    const float* U   = (const float*)d_in[3];
    const float* b   = (const float*)d_in[4];
    const float* Wd  = (const float*)d_in[5];
    const float* bd  = (const float*)d_in[6];
    float* out = (float*)d_out;

    static cudaStream_t s2 = nullptr, s3 = nullptr;
    static cudaEvent_t eFork = nullptr, eWdt = nullptr, eS0 = nullptr,
                       eS1 = nullptr, eDone = nullptr;
    if (!s2) {
        cudaStreamCreateWithFlags(&s2, cudaStreamNonBlocking);
        cudaStreamCreateWithFlags(&s3, cudaStreamNonBlocking);
        cudaEventCreateWithFlags(&eFork, cudaEventDisableTiming);
        cudaEventCreateWithFlags(&eWdt,  cudaEventDisableTiming);
        cudaEventCreateWithFlags(&eS0,   cudaEventDisableTiming);
        cudaEventCreateWithFlags(&eS1,   cudaEventDisableTiming);
        cudaEventCreateWithFlags(&eDone, cudaEventDisableTiming);
        cudaFuncSetAttribute(k_gemm, cudaFuncAttributeMaxDynamicSharedMemorySize, SM_TOTAL);
    }

    cudaEventRecord(eFork, 0);
    cudaStreamWaitEvent(s2, eFork, 0);
    k_wdt<<<dim3(VPAD / 32, HID / 32), dim3(32, 8), 0, s2>>>(Wd);
    cudaEventRecord(eWdt, s2);

    k_detect<<<1, 256>>>((const unsigned int*)ids);
    k_embed<<<ROWS / 16, 128>>>(ids, emb, W, b);

    k_scan<<<BATCH, HID>>>(U, 0);
    cudaEventRecord(eS0, 0);
    k_scan<<<BATCH, HID>>>(U, TCH);       // runs concurrent with gemm chunk 0
    cudaEventRecord(eS1, 0);

    cudaStreamWaitEvent(s3, eWdt, 0);
    cudaStreamWaitEvent(s3, eS0, 0);
    k_gemm<<<dim3(VPAD / 256, BATCH / 4), 256, SM_TOTAL, s3>>>(bd, out, 0);
    cudaStreamWaitEvent(s3, eS1, 0);
    k_gemm<<<dim3(VPAD / 256, BATCH / 4), 256, SM_TOTAL, s3>>>(bd, out, TCH);
    cudaEventRecord(eDone, s3);
    cudaStreamWaitEvent(0, eDone, 0);
}

// round 9
// speedup vs baseline: 1.4392x; 1.0622x over previous
#include <cuda_runtime.h>
#include <cuda_fp16.h>
#include <cstdint>

// ---------------------------------------------------------------------------
// Problem constants
// ---------------------------------------------------------------------------
#define VOCAB 10000
#define VPAD  10240          // 40 * 256
#define EMB   64
#define HID   128
#define BATCH 32
#define TLEN  256
#define TCH   64             // timestep chunk (4 chunks)
#define ROWS  (BATCH * TLEN) // 8192

// ---------------------------------------------------------------------------
// Device scratch (no allocation allowed)
// ---------------------------------------------------------------------------
__device__ __align__(16) float   g_xw[ROWS * HID];       // 4 MB
__device__ __align__(16) __half  g_rnn_h[ROWS * HID];    // 2 MB
__device__ __align__(16) __half  g_wdt_h[VPAD * HID];    // 2.6 MB
__device__ __align__(16) float   g_hst[BATCH * HID];     // scan state hand-off
__device__ int g_ids_is64;

// ---------------------------------------------------------------------------
// PTX helpers (plain-target instructions only; no tcgen05)
// ---------------------------------------------------------------------------
__device__ __forceinline__ uint32_t smem_u32(const void* p) {
    uint32_t a;
    asm("{ .reg .u64 t; cvta.to.shared.u64 t, %1; cvt.u32.u64 %0, t; }" : "=r"(a) : "l"(p));
    return a;
}
__device__ __forceinline__ void ldsm_x4(uint32_t* r, uint32_t addr) {
    asm volatile("ldmatrix.sync.aligned.m8n8.x4.shared.b16 {%0,%1,%2,%3}, [%4];"
                 : "=r"(r[0]), "=r"(r[1]), "=r"(r[2]), "=r"(r[3]) : "r"(addr));
}
__device__ __forceinline__ void mma16816(float* c, const uint32_t* a,
                                         uint32_t b0, uint32_t b1) {
    asm volatile("mma.sync.aligned.m16n8k16.row.col.f32.f16.f16.f32 "
                 "{%0,%1,%2,%3}, {%4,%5,%6,%7}, {%8,%9}, {%0,%1,%2,%3};"
                 : "+f"(c[0]), "+f"(c[1]), "+f"(c[2]), "+f"(c[3])
                 : "r"(a[0]), "r"(a[1]), "r"(a[2]), "r"(a[3]), "r"(b0), "r"(b1));
}
__device__ __forceinline__ void cp16(uint32_t dst, const void* src) {
    asm volatile("cp.async.cg.shared.global [%0], [%1], 16;" :: "r"(dst), "l"(src));
}
#define CP_COMMIT()  asm volatile("cp.async.commit_group;" ::: "memory")
#define CP_WAIT(N)   asm volatile("cp.async.wait_group %0;" :: "n"(N) : "memory")

// packed f32x2 ops
__device__ __forceinline__ void fma2(unsigned long long& acc,
                                     unsigned long long a, unsigned long long b) {
    asm("fma.rn.f32x2 %0, %1, %2, %0;" : "+l"(acc) : "l"(a), "l"(b));
}
__device__ __forceinline__ unsigned long long add2(unsigned long long a,
                                                   unsigned long long b) {
    unsigned long long d;
    asm("add.rn.f32x2 %0, %1, %2;" : "=l"(d) : "l"(a), "l"(b));
    return d;
}
__device__ __forceinline__ unsigned long long pack2(float x, float y) {
    unsigned long long p;
    asm("mov.b64 %0, {%1, %2};" : "=l"(p) : "f"(x), "f"(y));
    return p;
}
__device__ __forceinline__ void unpack2(unsigned long long p, float& x, float& y) {
    asm("mov.b64 {%0, %1}, %2;" : "=f"(x), "=f"(y) : "l"(p));
}

// ---------------------------------------------------------------------------
// Kernel 0: detect inp_ids dtype (int64 vs int32) via odd 32-bit words
// ---------------------------------------------------------------------------
__global__ void k_detect(const unsigned int* __restrict__ w) {
    __shared__ int any;
    if (threadIdx.x == 0) any = 0;
    __syncthreads();
    unsigned int x = 0;
    for (int i = threadIdx.x; i < 2048; i += 256) x |= w[2 * i + 1];
    if (x) atomicOr(&any, 1);
    __syncthreads();
    if (threadIdx.x == 0) g_ids_is64 = any ? 0 : 1;
}

// ---------------------------------------------------------------------------
// Kernel 1: transpose Wd -> WdT[v][k] fp16, zero-padded to VPAD
// ---------------------------------------------------------------------------
__global__ void k_wdt(const float* __restrict__ Wd) {
    __shared__ float tile[32][33];
    int n0 = blockIdx.x * 32;   // vocab
    int k0 = blockIdx.y * 32;   // hid
    int tx = threadIdx.x, ty = threadIdx.y;  // 32 x 8
    #pragma unroll
    for (int i = 0; i < 32; i += 8) {
        int k = k0 + ty + i, n = n0 + tx;
        tile[ty + i][tx] = (n < VOCAB) ? Wd[(size_t)k * VOCAB + n] : 0.f;
    }
    __syncthreads();
    #pragma unroll
    for (int i = 0; i < 32; i += 8) {
        int n = n0 + ty + i, k = k0 + tx;
        g_wdt_h[n * HID + k] = __float2half(tile[tx][ty + i]);
    }
}

// ---------------------------------------------------------------------------
// Kernel 2: embedding lookup + input projection for a timestep range.
// grid = BATCH * (t_len/16) blocks of 16 rows.
// ---------------------------------------------------------------------------
__global__ void k_embed(const void* __restrict__ ids_raw,
                        const float* __restrict__ emb,
                        const float* __restrict__ W,
                        const float* __restrict__ b,
                        int t_base, int t_blocks) {
    __shared__ float Ws[EMB * HID];
    __shared__ float xs[16][EMB];
    int j = threadIdx.x;
    int is64 = g_ids_is64;
    for (int i = j; i < EMB * HID; i += 128) Ws[i] = W[i];
    int bb   = blockIdx.x / t_blocks;
    int tloc = (blockIdx.x % t_blocks) * 16;
    int r0   = bb * TLEN + t_base + tloc;
    for (int p = j; p < 16 * EMB; p += 128) {
        int ri = p >> 6, e = p & 63;
        long long id = is64 ? ((const long long*)ids_raw)[r0 + ri]
                            : (long long)((const int*)ids_raw)[r0 + ri];
        xs[ri][e] = emb[id * EMB + e];
    }
    __syncthreads();
    float bj = b[j];
    #pragma unroll 1
    for (int ri = 0; ri < 16; ri++) {
        float a0 = bj, a1 = 0.f;
        #pragma unroll
        for (int e = 0; e < EMB; e += 2) {
            a0 += xs[ri][e]     * Ws[e * HID + j];
            a1 += xs[ri][e + 1] * Ws[(e + 1) * HID + j];
        }
        g_xw[(r0 + ri) * HID + j] = a0 + a1;
    }
}

// ---------------------------------------------------------------------------
// Kernel 3: RNN scan CHUNK of TCH steps. 1 batch/CTA, 128 thr. State carried
// through g_hst (fp32, exact) so each chunk continues bit-identically.
// fp16 emission happens after the barrier (off the critical path).
// ---------------------------------------------------------------------------
__global__ void __launch_bounds__(HID, 1) k_scan(const float* __restrict__ U, int t0) {
    __shared__ __align__(16) float h[2][HID];
    int bb = blockIdx.x;
    int j  = threadIdx.x;

    unsigned long long u2[HID / 2];
    #pragma unroll
    for (int q = 0; q < HID / 2; q++)
        u2[q] = pack2(U[(2 * q) * HID + j], U[(2 * q + 1) * HID + j]);

    float h0 = (t0 == 0) ? 0.f : g_hst[bb * HID + j];
    h[0][j] = h0;
    __syncthreads();

    const float* xwp  = g_xw    + ((size_t)bb * TLEN + t0) * HID + j;
    __half*      outp = g_rnn_h + ((size_t)bb * TLEN + t0) * HID + j;
    float xw_cur = xwp[0];
    int buf = 0;
    float h_prev = 0.f;
    int   emit   = 0;

    #pragma unroll 1
    for (int t = 0; t < TCH; t++) {
        float xw_next = (t < TCH - 1) ? xwp[(t + 1) * HID] : 0.f;

        unsigned long long a[8];
        a[0] = pack2(xw_cur, 0.f);
        #pragma unroll
        for (int q = 1; q < 8; q++) a[q] = 0ull;

        const ulonglong2* hp = (const ulonglong2*)&h[buf][0];
        #pragma unroll
        for (int i = 0; i < 32; i++) {
            ulonglong2 hv = hp[i];
            fma2(a[(2 * i) & 7],     u2[2 * i],     hv.x);
            fma2(a[(2 * i + 1) & 7], u2[2 * i + 1], hv.y);
        }
        unsigned long long r0 = add2(a[0], a[1]);
        unsigned long long r1 = add2(a[2], a[3]);
        unsigned long long r2 = add2(a[4], a[5]);
        unsigned long long r3 = add2(a[6], a[7]);
        unsigned long long s  = add2(add2(r0, r1), add2(r2, r3));
        float zx, zy;
        unpack2(s, zx, zy);
        float z = zx + zy;

        float e = __expf(2.f * z);
        float hval = 1.f - __fdividef(2.f, e + 1.f);

        h[buf ^ 1][j] = hval;              // STS first: only thing the barrier gates
        __syncthreads();

        if (emit) outp[(t - 1) * HID] = __float2half(h_prev);
        h_prev = hval;
        emit = 1;
        buf ^= 1;
        xw_cur = xw_next;
    }
    outp[(TCH - 1) * HID] = __float2half(h_prev);
    g_hst[bb * HID + j] = h_prev;          // state hand-off (exact fp32)
}

// ---------------------------------------------------------------------------
// Kernel 4: output GEMM chunk (timesteps [t0, t0+64) of every batch).
// A-tile (128 rows) = 2 batches' 64-row segments; the warp M-split (wm*64)
// falls exactly on the segment boundary. B (v-tile 256) resident, 2 A-tiles
// per CTA double-buffered via cp.async. Grid (40, 8) per chunk.
// ---------------------------------------------------------------------------
#define SB_BYTES   65536                 // 256 rows x 256B (fp16)
#define SA_BYTES   32768                 // per stage: 128 rows x 256B
#define N_TILES    2
#define SM_TOTAL   (SB_BYTES + N_TILES * SA_BYTES)   // 128 KB

__device__ __forceinline__ void gemm_load_a(uint32_t sAbuf, int row0a, int row0b,
                                            int tid) {
    #pragma unroll
    for (int i = tid; i < 2048; i += 256) {       // 128 rows x 16 chunks
        int row = i >> 4, ch = i & 15;
        int gr = (row < 64) ? (row0a + row) : (row0b + row - 64);
        uint32_t dst = sAbuf + row * 256 + ((ch ^ (row & 7)) << 4);
        cp16(dst, g_rnn_h + (size_t)gr * HID + ch * 8);
    }
}

__global__ void __launch_bounds__(256, 1) k_gemm(const float* __restrict__ bd,
                                                 float* __restrict__ out, int t0) {
    extern __shared__ char smem[];
    uint32_t sB  = smem_u32(smem);
    uint32_t sA0 = sB + SB_BYTES;

    int tid  = threadIdx.x;
    int wid  = tid >> 5;
    int lane = tid & 31;
    int v0   = blockIdx.x * 256;
    int bg   = blockIdx.y * (2 * N_TILES);  // first batch of this CTA's 4

    // ---- prologue: B (resident) + A0 in group 0; A1 in group 1 ----
    #pragma unroll
    for (int i = tid; i < 4096; i += 256) {       // B: 256 rows x 16 chunks
        int row = i >> 4, ch = i & 15;
        uint32_t dst = sB + row * 256 + ((ch ^ (row & 7)) << 4);
        cp16(dst, g_wdt_h + (size_t)(v0 + row) * HID + ch * 8);
    }
    gemm_load_a(sA0, bg * TLEN + t0, (bg + 1) * TLEN + t0, tid);
    CP_COMMIT();
    gemm_load_a(sA0 + SA_BYTES, (bg + 2) * TLEN + t0, (bg + 3) * TLEN + t0, tid);
    CP_COMMIT();

    int wm = wid & 1;          // 2 warps over bt (64 each = one batch segment)
    int wn = wid >> 1;         // 4 warps over v  (64 each)
    int rA  = ((lane >> 3) & 1) * 8 + (lane & 7);
    int kcA = lane >> 4;
    int rB  = ((lane >> 4) & 1) * 8 + (lane & 7);
    int kcB = (lane >> 3) & 1;
    int lx  = lane & 7;

    #pragma unroll 1
    for (int it = 0; it < N_TILES; it++) {
        if (it == 0) { CP_WAIT(1); } else { CP_WAIT(0); }
        __syncthreads();

        uint32_t sAb = sA0 + it * SA_BYTES;
        // this warp's batch segment: base row in g_rnn/out coordinates
        int rbase = (bg + 2 * it + wm) * TLEN + t0;

        float c[4][8][4];
        #pragma unroll
        for (int mb = 0; mb < 4; mb++)
            #pragma unroll
            for (int nb = 0; nb < 8; nb++)
                #pragma unroll
                for (int q = 0; q < 4; q++) c[mb][nb][q] = 0.f;

        uint32_t aBase = sAb + (uint32_t)(wm * 64 + rA) * 256;
        uint32_t bBase = sB  + (uint32_t)(wn * 64 + rB) * 256;
        #pragma unroll 1
        for (int ks = 0; ks < 8; ks++) {
            uint32_t a[4][4], b[4][4];
            int kA = (ks * 2 + kcA) ^ lx;
            int kB = (ks * 2 + kcB) ^ lx;
            #pragma unroll
            for (int mb = 0; mb < 4; mb++)
                ldsm_x4(a[mb], aBase + (uint32_t)(mb * 16) * 256 + (kA << 4));
            #pragma unroll
            for (int nb = 0; nb < 4; nb++)
                ldsm_x4(b[nb], bBase + (uint32_t)(nb * 16) * 256 + (kB << 4));
            #pragma unroll
            for (int mb = 0; mb < 4; mb++)
                #pragma unroll
                for (int nbi = 0; nbi < 8; nbi++)
                    mma16816(c[mb][nbi], a[mb],
                             b[nbi >> 1][(nbi & 1) * 2],
                             b[nbi >> 1][(nbi & 1) * 2 + 1]);
        }
        __syncthreads();

        // ---- epilogue: bias + store ----
        #pragma unroll
        for (int nbi = 0; nbi < 8; nbi++) {
            int col = v0 + wn * 64 + nbi * 8 + (lane & 3) * 2;
            if (col < VOCAB) {
                float b0 = bd[col], b1 = bd[col + 1];
                #pragma unroll
                for (int mb = 0; mb < 4; mb++) {
                    int r = rbase + mb * 16 + (lane >> 2);
                    float2 lo = make_float2(c[mb][nbi][0] + b0, c[mb][nbi][1] + b1);
                    float2 hi = make_float2(c[mb][nbi][2] + b0, c[mb][nbi][3] + b1);
                    *(float2*)(out + (size_t)r * VOCAB + col) = lo;
                    *(float2*)(out + (size_t)(r + 8) * VOCAB + col) = hi;
                }
            }
        }
    }
}

// ---------------------------------------------------------------------------
// Launch: s2 = wdt + embed-rest; main = detect + embed-head + 4 scan chunks;
// s3 = 4 gemm chunks, each gated on its scan chunk. Join to main at the end.
// ---------------------------------------------------------------------------
extern "C" void kernel_launch(void* const* d_in, const int* in_sizes, int n_in,
                              void* d_out, int out_size) {
    const void*  ids = d_in[0];
    const float* emb = (const float*)d_in[1];
    const float* W   = (const float*)d_in[2];
    const float* U   = (const float*)d_in[3];
    const float* b   = (const float*)d_in[4];
    const float* Wd  = (const float*)d_in[5];
    const float* bd  = (const float*)d_in[6];
    float* out = (float*)d_out;

    static cudaStream_t s2 = nullptr, s3 = nullptr;
    static cudaEvent_t eFork = nullptr, eWdt = nullptr, eE0 = nullptr,
                       eErest = nullptr, eS[4] = {}, eDone = nullptr;
    if (!s2) {
        cudaStreamCreateWithFlags(&s2, cudaStreamNonBlocking);
        cudaStreamCreateWithFlags(&s3, cudaStreamNonBlocking);
        cudaEventCreateWithFlags(&eFork,  cudaEventDisableTiming);
        cudaEventCreateWithFlags(&eWdt,   cudaEventDisableTiming);
        cudaEventCreateWithFlags(&eE0,    cudaEventDisableTiming);
        cudaEventCreateWithFlags(&eErest, cudaEventDisableTiming);
        for (int i = 0; i < 4; i++) cudaEventCreateWithFlags(&eS[i], cudaEventDisableTiming);
        cudaEventCreateWithFlags(&eDone,  cudaEventDisableTiming);
        cudaFuncSetAttribute(k_gemm, cudaFuncAttributeMaxDynamicSharedMemorySize, SM_TOTAL);
    }

    cudaEventRecord(eFork, 0);
    cudaStreamWaitEvent(s2, eFork, 0);
    k_wdt<<<dim3(VPAD / 32, HID / 32), dim3(32, 8), 0, s2>>>(Wd);
    cudaEventRecord(eWdt, s2);

    // main: detect + embed head (t < TCH) -> S0 can start ASAP
    k_detect<<<1, 256>>>((const unsigned int*)ids);
    k_embed<<<BATCH * (TCH / 16), 128>>>(ids, emb, W, b, 0, TCH / 16);
    cudaEventRecord(eE0, 0);

    // s2: embed rest (t in [TCH, TLEN)) concurrent with S0
    cudaStreamWaitEvent(s2, eE0, 0);
    k_embed<<<BATCH * ((TLEN - TCH) / 16), 128, 0, s2>>>(ids, emb, W, b,
                                                         TCH, (TLEN - TCH) / 16);
    cudaEventRecord(eErest, s2);

    // main: scan chunks (serial dependency chain)
    k_scan<<<BATCH, HID>>>(U, 0);
    cudaEventRecord(eS[0], 0);
    cudaStreamWaitEvent(0, eErest, 0);
    for (int q = 1; q < 4; q++) {
        k_scan<<<BATCH, HID>>>(U, q * TCH);
        cudaEventRecord(eS[q], 0);
    }

    // s3: gemm chunks, each gated on its scan chunk
    cudaStreamWaitEvent(s3, eWdt, 0);
    for (int q = 0; q < 4; q++) {
        cudaStreamWaitEvent(s3, eS[q], 0);
        k_gemm<<<dim3(VPAD / 256, BATCH / (2 * N_TILES)), 256, SM_TOTAL, s3>>>(
            bd, out, q * TCH);
    }
    cudaEventRecord(eDone, s3);
    cudaStreamWaitEvent(0, eDone, 0);
}

// round 10
// speedup vs baseline: 1.5391x; 1.0694x over previous
#include <cuda_runtime.h>
#include <cuda_fp16.h>
#include <cstdint>

// ---------------------------------------------------------------------------
// Problem constants
// ---------------------------------------------------------------------------
#define VOCAB 10000
#define VPAD  10240          // 40 * 256
#define EMB   64
#define HID   128
#define BATCH 32
#define TLEN  256
#define ROWS  (BATCH * TLEN) // 8192

// ---------------------------------------------------------------------------
// Device scratch (no allocation allowed)
// ---------------------------------------------------------------------------
__device__ __align__(16) float   g_xw[ROWS * HID];       // 4 MB
__device__ __align__(16) __half  g_rnn_h[ROWS * HID];    // 2 MB
__device__ __align__(16) __half  g_wdt_h[VPAD * HID];    // 2.6 MB
__device__ __align__(16) float   g_hst[BATCH * HID];     // scan state hand-off
__device__ int g_ids_is64;

// ---------------------------------------------------------------------------
// PTX helpers (plain-target instructions only; no tcgen05)
// ---------------------------------------------------------------------------
__device__ __forceinline__ uint32_t smem_u32(const void* p) {
    uint32_t a;
    asm("{ .reg .u64 t; cvta.to.shared.u64 t, %1; cvt.u32.u64 %0, t; }" : "=r"(a) : "l"(p));
    return a;
}
__device__ __forceinline__ void ldsm_x4(uint32_t* r, uint32_t addr) {
    asm volatile("ldmatrix.sync.aligned.m8n8.x4.shared.b16 {%0,%1,%2,%3}, [%4];"
                 : "=r"(r[0]), "=r"(r[1]), "=r"(r[2]), "=r"(r[3]) : "r"(addr));
}
__device__ __forceinline__ void mma16816(float* c, const uint32_t* a,
                                         uint32_t b0, uint32_t b1) {
    asm volatile("mma.sync.aligned.m16n8k16.row.col.f32.f16.f16.f32 "
                 "{%0,%1,%2,%3}, {%4,%5,%6,%7}, {%8,%9}, {%0,%1,%2,%3};"
                 : "+f"(c[0]), "+f"(c[1]), "+f"(c[2]), "+f"(c[3])
                 : "r"(a[0]), "r"(a[1]), "r"(a[2]), "r"(a[3]), "r"(b0), "r"(b1));
}
__device__ __forceinline__ void cp16(uint32_t dst, const void* src) {
    asm volatile("cp.async.cg.shared.global [%0], [%1], 16;" :: "r"(dst), "l"(src));
}
#define CP_COMMIT()  asm volatile("cp.async.commit_group;" ::: "memory")
#define CP_WAIT(N)   asm volatile("cp.async.wait_group %0;" :: "n"(N) : "memory")

// packed f32x2 ops
__device__ __forceinline__ void fma2(unsigned long long& acc,
                                     unsigned long long a, unsigned long long b) {
    asm("fma.rn.f32x2 %0, %1, %2, %0;" : "+l"(acc) : "l"(a), "l"(b));
}
__device__ __forceinline__ unsigned long long add2(unsigned long long a,
                                                   unsigned long long b) {
    unsigned long long d;
    asm("add.rn.f32x2 %0, %1, %2;" : "=l"(d) : "l"(a), "l"(b));
    return d;
}
__device__ __forceinline__ unsigned long long pack2(float x, float y) {
    unsigned long long p;
    asm("mov.b64 %0, {%1, %2};" : "=l"(p) : "f"(x), "f"(y));
    return p;
}
__device__ __forceinline__ void unpack2(unsigned long long p, float& x, float& y) {
    asm("mov.b64 {%0, %1}, %2;" : "=f"(x), "=f"(y) : "l"(p));
}

// ---------------------------------------------------------------------------
// Kernel 0: detect inp_ids dtype (int64 vs int32) via odd 32-bit words
// ---------------------------------------------------------------------------
__global__ void k_detect(const unsigned int* __restrict__ w) {
    __shared__ int any;
    if (threadIdx.x == 0) any = 0;
    __syncthreads();
    unsigned int x = 0;
    for (int i = threadIdx.x; i < 2048; i += 256) x |= w[2 * i + 1];
    if (x) atomicOr(&any, 1);
    __syncthreads();
    if (threadIdx.x == 0) g_ids_is64 = any ? 0 : 1;
}

// ---------------------------------------------------------------------------
// Kernel 1: transpose Wd -> WdT[v][k] fp16, zero-padded to VPAD
// ---------------------------------------------------------------------------
__global__ void k_wdt(const float* __restrict__ Wd) {
    __shared__ float tile[32][33];
    int n0 = blockIdx.x * 32;   // vocab
    int k0 = blockIdx.y * 32;   // hid
    int tx = threadIdx.x, ty = threadIdx.y;  // 32 x 8
    #pragma unroll
    for (int i = 0; i < 32; i += 8) {
        int k = k0 + ty + i, n = n0 + tx;
        tile[ty + i][tx] = (n < VOCAB) ? Wd[(size_t)k * VOCAB + n] : 0.f;
    }
    __syncthreads();
    #pragma unroll
    for (int i = 0; i < 32; i += 8) {
        int n = n0 + ty + i, k = k0 + tx;
        g_wdt_h[n * HID + k] = __float2half(tile[tx][ty + i]);
    }
}

// ---------------------------------------------------------------------------
// Kernel 2: embedding lookup + input projection for a timestep range
// ---------------------------------------------------------------------------
__global__ void k_embed(const void* __restrict__ ids_raw,
                        const float* __restrict__ emb,
                        const float* __restrict__ W,
                        const float* __restrict__ b,
                        int t_base, int t_blocks) {
    __shared__ float Ws[EMB * HID];
    __shared__ float xs[16][EMB];
    int j = threadIdx.x;
    int is64 = g_ids_is64;
    for (int i = j; i < EMB * HID; i += 128) Ws[i] = W[i];
    int bb   = blockIdx.x / t_blocks;
    int tloc = (blockIdx.x % t_blocks) * 16;
    int r0   = bb * TLEN + t_base + tloc;
    for (int p = j; p < 16 * EMB; p += 128) {
        int ri = p >> 6, e = p & 63;
        long long id = is64 ? ((const long long*)ids_raw)[r0 + ri]
                            : (long long)((const int*)ids_raw)[r0 + ri];
        xs[ri][e] = emb[id * EMB + e];
    }
    __syncthreads();
    float bj = b[j];
    #pragma unroll 1
    for (int ri = 0; ri < 16; ri++) {
        float a0 = bj, a1 = 0.f;
        #pragma unroll
        for (int e = 0; e < EMB; e += 2) {
            a0 += xs[ri][e]     * Ws[e * HID + j];
            a1 += xs[ri][e + 1] * Ws[(e + 1) * HID + j];
        }
        g_xw[(r0 + ri) * HID + j] = a0 + a1;
    }
}

// ---------------------------------------------------------------------------
// Kernel 3: RNN scan chunk of tch steps. 1 batch/CTA, 128 thr. State carried
// through g_hst (fp32, exact) so each chunk continues bit-identically.
// ---------------------------------------------------------------------------
__global__ void __launch_bounds__(HID, 1) k_scan(const float* __restrict__ U,
                                                 int t0, int tch) {
    __shared__ __align__(16) float h[2][HID];
    int bb = blockIdx.x;
    int j  = threadIdx.x;

    unsigned long long u2[HID / 2];
    #pragma unroll
    for (int q = 0; q < HID / 2; q++)
        u2[q] = pack2(U[(2 * q) * HID + j], U[(2 * q + 1) * HID + j]);

    float h0 = (t0 == 0) ? 0.f : g_hst[bb * HID + j];
    h[0][j] = h0;
    __syncthreads();

    const float* xwp  = g_xw    + ((size_t)bb * TLEN + t0) * HID + j;
    __half*      outp = g_rnn_h + ((size_t)bb * TLEN + t0) * HID + j;
    float xw_cur = xwp[0];
    int buf = 0;
    float h_prev = 0.f;
    int   emit   = 0;

    #pragma unroll 1
    for (int t = 0; t < tch; t++) {
        float xw_next = (t < tch - 1) ? xwp[(t + 1) * HID] : 0.f;

        unsigned long long a[8];
        a[0] = pack2(xw_cur, 0.f);
        #pragma unroll
        for (int q = 1; q < 8; q++) a[q] = 0ull;

        const ulonglong2* hp = (const ulonglong2*)&h[buf][0];
        #pragma unroll
        for (int i = 0; i < 32; i++) {
            ulonglong2 hv = hp[i];
            fma2(a[(2 * i) & 7],     u2[2 * i],     hv.x);
            fma2(a[(2 * i + 1) & 7], u2[2 * i + 1], hv.y);
        }
        unsigned long long r0 = add2(a[0], a[1]);
        unsigned long long r1 = add2(a[2], a[3]);
        unsigned long long r2 = add2(a[4], a[5]);
        unsigned long long r3 = add2(a[6], a[7]);
        unsigned long long s  = add2(add2(r0, r1), add2(r2, r3));
        float zx, zy;
        unpack2(s, zx, zy);
        float z = zx + zy;

        float e = __expf(2.f * z);
        float hval = 1.f - __fdividef(2.f, e + 1.f);

        h[buf ^ 1][j] = hval;              // STS first: only thing the barrier gates
        __syncthreads();

        if (emit) outp[(t - 1) * HID] = __float2half(h_prev);
        h_prev = hval;
        emit = 1;
        buf ^= 1;
        xw_cur = xw_next;
    }
    outp[(tch - 1) * HID] = __float2half(h_prev);
    g_hst[bb * HID + j] = h_prev;          // state hand-off (exact fp32)
}

// ---------------------------------------------------------------------------
// Kernel 4: output GEMM chunk (timesteps [t0, t0+TL) of every batch).
// Templated on TL (segment length 32 or 64): A-tile 128 rows = (128/TL)
// batches' TL-row segments. B (v-tile 256) resident, 2 A-tiles per CTA
// double-buffered. Grid (40, BATCH*TL/256) per chunk.
// ---------------------------------------------------------------------------
#define SB_BYTES   65536                 // 256 rows x 256B (fp16)
#define SA_BYTES   32768                 // per stage: 128 rows x 256B
#define N_TILES    2
#define SM_TOTAL   (SB_BYTES + N_TILES * SA_BYTES)   // 128 KB

template<int TL>
__device__ __forceinline__ void gemm_load_a(uint32_t sAbuf, int bstart, int t0,
                                            int tid) {
    #pragma unroll
    for (int i = tid; i < 2048; i += 256) {       // 128 rows x 16 chunks
        int row = i >> 4, ch = i & 15;
        int gr = (bstart + row / TL) * TLEN + t0 + (row & (TL - 1));
        uint32_t dst = sAbuf + row * 256 + ((ch ^ (row & 7)) << 4);
        cp16(dst, g_rnn_h + (size_t)gr * HID + ch * 8);
    }
}

template<int TL>
__global__ void __launch_bounds__(256, 1) k_gemm(const float* __restrict__ bd,
                                                 float* __restrict__ out, int t0) {
    extern __shared__ char smem[];
    uint32_t sB  = smem_u32(smem);
    uint32_t sA0 = sB + SB_BYTES;

    int tid  = threadIdx.x;
    int wid  = tid >> 5;
    int lane = tid & 31;
    int v0   = blockIdx.x * 256;
    const int BPT = 128 / TL;               // batches per A-tile
    int bg   = blockIdx.y * (N_TILES * BPT);

    // ---- prologue: B (resident) + A0 in group 0; A1 in group 1 ----
    #pragma unroll
    for (int i = tid; i < 4096; i += 256) {       // B: 256 rows x 16 chunks
        int row = i >> 4, ch = i & 15;
        uint32_t dst = sB + row * 256 + ((ch ^ (row & 7)) << 4);
        cp16(dst, g_wdt_h + (size_t)(v0 + row) * HID + ch * 8);
    }
    gemm_load_a<TL>(sA0, bg, t0, tid);
    CP_COMMIT();
    gemm_load_a<TL>(sA0 + SA_BYTES, bg + BPT, t0, tid);
    CP_COMMIT();

    int wm = wid & 1;          // 2 warps over the 128 A rows (64 each)
    int wn = wid >> 1;         // 4 warps over v (64 each)
    int rA  = ((lane >> 3) & 1) * 8 + (lane & 7);
    int kcA = lane >> 4;
    int rB  = ((lane >> 4) & 1) * 8 + (lane & 7);
    int kcB = (lane >> 3) & 1;
    int lx  = lane & 7;

    #pragma unroll 1
    for (int it = 0; it < N_TILES; it++) {
        if (it == 0) { CP_WAIT(1); } else { CP_WAIT(0); }
        __syncthreads();

        uint32_t sAb = sA0 + it * SA_BYTES;
        int btile = bg + it * BPT;            // first batch of this A-tile

        float c[4][8][4];
        #pragma unroll
        for (int mb = 0; mb < 4; mb++)
            #pragma unroll
            for (int nb = 0; nb < 8; nb++)
                #pragma unroll
                for (int q = 0; q < 4; q++) c[mb][nb][q] = 0.f;

        uint32_t aBase = sAb + (uint32_t)(wm * 64 + rA) * 256;
        uint32_t bBase = sB  + (uint32_t)(wn * 64 + rB) * 256;
        #pragma unroll 1
        for (int ks = 0; ks < 8; ks++) {
            uint32_t a[4][4], b[4][4];
            int kA = (ks * 2 + kcA) ^ lx;
            int kB = (ks * 2 + kcB) ^ lx;
            #pragma unroll
            for (int mb = 0; mb < 4; mb++)
                ldsm_x4(a[mb], aBase + (uint32_t)(mb * 16) * 256 + (kA << 4));
            #pragma unroll
            for (int nb = 0; nb < 4; nb++)
                ldsm_x4(b[nb], bBase + (uint32_t)(nb * 16) * 256 + (kB << 4));
            #pragma unroll
            for (int mb = 0; mb < 4; mb++)
                #pragma unroll
                for (int nbi = 0; nbi < 8; nbi++)
                    mma16816(c[mb][nbi], a[mb],
                             b[nbi >> 1][(nbi & 1) * 2],
                             b[nbi >> 1][(nbi & 1) * 2 + 1]);
        }
        __syncthreads();

        // ---- epilogue: bias + store ----
        #pragma unroll
        for (int nbi = 0; nbi < 8; nbi++) {
            int col = v0 + wn * 64 + nbi * 8 + (lane & 3) * 2;
            if (col < VOCAB) {
                float b0 = bd[col], b1 = bd[col + 1];
                #pragma unroll
                for (int mb = 0; mb < 4; mb++) {
                    int lr0 = wm * 64 + mb * 16;          // local A row of c[..][0]
                    int r = (btile + lr0 / TL) * TLEN + t0 + (lr0 & (TL - 1))
                          + (lane >> 2);
                    float2 lo = make_float2(c[mb][nbi][0] + b0, c[mb][nbi][1] + b1);
                    float2 hi = make_float2(c[mb][nbi][2] + b0, c[mb][nbi][3] + b1);
                    *(float2*)(out + (size_t)r * VOCAB + col) = lo;
                    *(float2*)(out + (size_t)(r + 8) * VOCAB + col) = hi;
                }
            }
        }
    }
}

// ---------------------------------------------------------------------------
// Launch: chunks (32,64,64,64,32). s2 = wdt; s4 also runs embed-rest early;
// gemm chunks alternate s3/s4, each gated only on its scan event.
// ---------------------------------------------------------------------------
extern "C" void kernel_launch(void* const* d_in, const int* in_sizes, int n_in,
                              void* d_out, int out_size) {
    const void*  ids = d_in[0];
    const float* emb = (const float*)d_in[1];
    const float* W   = (const float*)d_in[2];
    const float* U   = (const float*)d_in[3];
    const float* b   = (const float*)d_in[4];
    const float* Wd  = (const float*)d_in[5];
    const float* bd  = (const float*)d_in[6];
    float* out = (float*)d_out;

    static cudaStream_t s2 = nullptr, s3 = nullptr, s4 = nullptr;
    static cudaEvent_t eD = nullptr, eFork = nullptr, eWdt = nullptr,
                       eEr1 = nullptr, eEr2 = nullptr,
                       eS[5] = {}, eG3 = nullptr, eG4 = nullptr;
    if (!s2) {
        cudaStreamCreateWithFlags(&s2, cudaStreamNonBlocking);
        cudaStreamCreateWithFlags(&s3, cudaStreamNonBlocking);
        cudaStreamCreateWithFlags(&s4, cudaStreamNonBlocking);
        cudaEventCreateWithFlags(&eD,    cudaEventDisableTiming);
        cudaEventCreateWithFlags(&eFork, cudaEventDisableTiming);
        cudaEventCreateWithFlags(&eWdt,  cudaEventDisableTiming);
        cudaEventCreateWithFlags(&eEr1,  cudaEventDisableTiming);
        cudaEventCreateWithFlags(&eEr2,  cudaEventDisableTiming);
        for (int i = 0; i < 5; i++) cudaEventCreateWithFlags(&eS[i], cudaEventDisableTiming);
        cudaEventCreateWithFlags(&eG3, cudaEventDisableTiming);
        cudaEventCreateWithFlags(&eG4, cudaEventDisableTiming);
        cudaFuncSetAttribute(k_gemm<64>, cudaFuncAttributeMaxDynamicSharedMemorySize, SM_TOTAL);
        cudaFuncSetAttribute(k_gemm<32>, cudaFuncAttributeMaxDynamicSharedMemorySize, SM_TOTAL);
    }

    // side stream s2: Wd transpose
    cudaEventRecord(eFork, 0);
    cudaStreamWaitEvent(s2, eFork, 0);
    k_wdt<<<dim3(VPAD / 32, HID / 32), dim3(32, 8), 0, s2>>>(Wd);
    cudaEventRecord(eWdt, s2);

    // main: detect + embed head (t < 32)
    k_detect<<<1, 256>>>((const unsigned int*)ids);
    cudaEventRecord(eD, 0);
    k_embed<<<BATCH * 2, 128>>>(ids, emb, W, b, 0, 2);

    // s4: embed rest, split so scan chunks are never starved
    cudaStreamWaitEvent(s4, eD, 0);
    k_embed<<<BATCH * 4,  128, 0, s4>>>(ids, emb, W, b, 32, 4);    // t in [32,96)
    cudaEventRecord(eEr1, s4);
    k_embed<<<BATCH * 10, 128, 0, s4>>>(ids, emb, W, b, 96, 10);   // t in [96,256)
    cudaEventRecord(eEr2, s4);

    // main: scan chunks 32,64,64,64,32
    static const int t0s[5]  = {0, 32, 96, 160, 224};
    static const int tchs[5] = {32, 64, 64, 64, 32};
    k_scan<<<BATCH, HID>>>(U, t0s[0], tchs[0]);
    cudaEventRecord(eS[0], 0);
    cudaStreamWaitEvent(0, eEr1, 0);
    k_scan<<<BATCH, HID>>>(U, t0s[1], tchs[1]);
    cudaEventRecord(eS[1], 0);
    cudaStreamWaitEvent(0, eEr2, 0);
    for (int q = 2; q < 5; q++) {
        k_scan<<<BATCH, HID>>>(U, t0s[q], tchs[q]);
        cudaEventRecord(eS[q], 0);
    }

    // gemm chunks: q even on s3, q odd on s4; each gated on eWdt + its scan
    cudaStreamWaitEvent(s3, eWdt, 0);
    cudaStreamWaitEvent(s4, eWdt, 0);

    cudaStreamWaitEvent(s3, eS[0], 0);
    k_gemm<32><<<dim3(VPAD / 256, 4), 256, SM_TOTAL, s3>>>(bd, out, t0s[0]);
    cudaStreamWaitEvent(s4, eS[1], 0);
    k_gemm<64><<<dim3(VPAD / 256, 8), 256, SM_TOTAL, s4>>>(bd, out, t0s[1]);
    cudaStreamWaitEvent(s3, eS[2], 0);
    k_gemm<64><<<dim3(VPAD / 256, 8), 256, SM_TOTAL, s3>>>(bd, out, t0s[2]);
    cudaStreamWaitEvent(s4, eS[3], 0);
    k_gemm<64><<<dim3(VPAD / 256, 8), 256, SM_TOTAL, s4>>>(bd, out, t0s[3]);
    cudaStreamWaitEvent(s3, eS[4], 0);
    k_gemm<32><<<dim3(VPAD / 256, 4), 256, SM_TOTAL, s3>>>(bd, out, t0s[4]);

    cudaEventRecord(eG3, s3);
    cudaEventRecord(eG4, s4);
    cudaStreamWaitEvent(0, eG3, 0);
    cudaStreamWaitEvent(0, eG4, 0);
}

// round 12
// speedup vs baseline: 1.6040x; 1.0422x over previous
#include <cuda_runtime.h>
#include <cuda_fp16.h>
#include <cstdint>

// ---------------------------------------------------------------------------
// Problem constants
// ---------------------------------------------------------------------------
#define VOCAB 10000
#define VPAD  10240          // 40 * 256
#define EMB   64
#define HID   128
#define BATCH 32
#define TLEN  256
#define ROWS  (BATCH * TLEN) // 8192

// ---------------------------------------------------------------------------
// Device scratch (no allocation allowed)
// ---------------------------------------------------------------------------
__device__ __align__(16) float   g_xw[ROWS * HID];       // 4 MB
__device__ __align__(16) __half  g_rnn_h[ROWS * HID];    // 2 MB
__device__ __align__(16) __half  g_wdt_h[VPAD * HID];    // 2.6 MB
__device__ __align__(16) float   g_hst[BATCH * HID];     // scan state hand-off
__device__ int g_ids_is64;

// ---------------------------------------------------------------------------
// PTX helpers (plain-target instructions only; no tcgen05)
// ---------------------------------------------------------------------------
__device__ __forceinline__ uint32_t smem_u32(const void* p) {
    uint32_t a;
    asm("{ .reg .u64 t; cvta.to.shared.u64 t, %1; cvt.u32.u64 %0, t; }" : "=r"(a) : "l"(p));
    return a;
}
__device__ __forceinline__ void ldsm_x4(uint32_t* r, uint32_t addr) {
    asm volatile("ldmatrix.sync.aligned.m8n8.x4.shared.b16 {%0,%1,%2,%3}, [%4];"
                 : "=r"(r[0]), "=r"(r[1]), "=r"(r[2]), "=r"(r[3]) : "r"(addr));
}
__device__ __forceinline__ void mma16816(float* c, const uint32_t* a,
                                         uint32_t b0, uint32_t b1) {
    asm volatile("mma.sync.aligned.m16n8k16.row.col.f32.f16.f16.f32 "
                 "{%0,%1,%2,%3}, {%4,%5,%6,%7}, {%8,%9}, {%0,%1,%2,%3};"
                 : "+f"(c[0]), "+f"(c[1]), "+f"(c[2]), "+f"(c[3])
                 : "r"(a[0]), "r"(a[1]), "r"(a[2]), "r"(a[3]), "r"(b0), "r"(b1));
}
__device__ __forceinline__ void cp16(uint32_t dst, const void* src) {
    asm volatile("cp.async.cg.shared.global [%0], [%1], 16;" :: "r"(dst), "l"(src));
}
#define CP_COMMIT()  asm volatile("cp.async.commit_group;" ::: "memory")
#define CP_WAIT(N)   asm volatile("cp.async.wait_group %0;" :: "n"(N) : "memory")

// packed f32x2 ops
__device__ __forceinline__ void fma2(unsigned long long& acc,
                                     unsigned long long a, unsigned long long b) {
    asm("fma.rn.f32x2 %0, %1, %2, %0;" : "+l"(acc) : "l"(a), "l"(b));
}
__device__ __forceinline__ unsigned long long add2(unsigned long long a,
                                                   unsigned long long b) {
    unsigned long long d;
    asm("add.rn.f32x2 %0, %1, %2;" : "=l"(d) : "l"(a), "l"(b));
    return d;
}
__device__ __forceinline__ unsigned long long pack2(float x, float y) {
    unsigned long long p;
    asm("mov.b64 %0, {%1, %2};" : "=l"(p) : "f"(x), "f"(y));
    return p;
}
__device__ __forceinline__ void unpack2(unsigned long long p, float& x, float& y) {
    asm("mov.b64 {%0, %1}, %2;" : "=f"(x), "=f"(y) : "l"(p));
}

// ---------------------------------------------------------------------------
// Kernel 0: detect inp_ids dtype (int64 vs int32) via odd 32-bit words
// ---------------------------------------------------------------------------
__global__ void k_detect(const unsigned int* __restrict__ w) {
    __shared__ int any;
    if (threadIdx.x == 0) any = 0;
    __syncthreads();
    unsigned int x = 0;
    for (int i = threadIdx.x; i < 2048; i += 256) x |= w[2 * i + 1];
    if (x) atomicOr(&any, 1);
    __syncthreads();
    if (threadIdx.x == 0) g_ids_is64 = any ? 0 : 1;
}

// ---------------------------------------------------------------------------
// Kernel 1: transpose Wd -> WdT[v][k] fp16, zero-padded to VPAD
// ---------------------------------------------------------------------------
__global__ void k_wdt(const float* __restrict__ Wd) {
    __shared__ float tile[32][33];
    int n0 = blockIdx.x * 32;   // vocab
    int k0 = blockIdx.y * 32;   // hid
    int tx = threadIdx.x, ty = threadIdx.y;  // 32 x 8
    #pragma unroll
    for (int i = 0; i < 32; i += 8) {
        int k = k0 + ty + i, n = n0 + tx;
        tile[ty + i][tx] = (n < VOCAB) ? Wd[(size_t)k * VOCAB + n] : 0.f;
    }
    __syncthreads();
    #pragma unroll
    for (int i = 0; i < 32; i += 8) {
        int n = n0 + ty + i, k = k0 + tx;
        g_wdt_h[n * HID + k] = __float2half(tile[tx][ty + i]);
    }
}

// ---------------------------------------------------------------------------
// Kernel 2: embed + input projection. 32 timesteps per 256-thread block;
// W column held in 64 registers; 4-row ILP accumulators; float4 xs reads.
// grid = BATCH * n32 blocks (block = one batch's 32-step span).
// ---------------------------------------------------------------------------
__global__ void __launch_bounds__(256, 1) k_embed(const void* __restrict__ ids_raw,
                                                  const float* __restrict__ emb,
                                                  const float* __restrict__ W,
                                                  const float* __restrict__ b,
                                                  int t_base, int n32) {
    __shared__ __align__(16) float xs[32][EMB];   // 8 KB
    int tid = threadIdx.x;
    int j   = tid & 127;       // hid unit
    int hh  = tid >> 7;        // row half (0/1)
    int is64 = g_ids_is64;

    int bb   = blockIdx.x / n32;
    int tloc = (blockIdx.x % n32) * 32;
    int r0   = bb * TLEN + t_base + tloc;

    float wreg[EMB];
    #pragma unroll
    for (int e = 0; e < EMB; e++) wreg[e] = W[e * HID + j];

    for (int p = tid; p < 32 * EMB; p += 256) {
        int ri = p >> 6, e = p & 63;
        long long id = is64 ? ((const long long*)ids_raw)[r0 + ri]
                            : (long long)((const int*)ids_raw)[r0 + ri];
        xs[ri][e] = emb[id * EMB + e];
    }
    __syncthreads();

    float bj = b[j];
    #pragma unroll
    for (int rg = 0; rg < 4; rg++) {
        int row = hh * 16 + rg * 4;
        float a0 = bj, a1 = bj, a2 = bj, a3 = bj;
        #pragma unroll
        for (int e = 0; e < EMB; e += 4) {
            float4 x0 = *(const float4*)&xs[row + 0][e];
            float4 x1 = *(const float4*)&xs[row + 1][e];
            float4 x2 = *(const float4*)&xs[row + 2][e];
            float4 x3 = *(const float4*)&xs[row + 3][e];
            a0 += x0.x * wreg[e] + x0.y * wreg[e + 1] + x0.z * wreg[e + 2] + x0.w * wreg[e + 3];
            a1 += x1.x * wreg[e] + x1.y * wreg[e + 1] + x1.z * wreg[e + 2] + x1.w * wreg[e + 3];
            a2 += x2.x * wreg[e] + x2.y * wreg[e + 1] + x2.z * wreg[e + 2] + x2.w * wreg[e + 3];
            a3 += x3.x * wreg[e] + x3.y * wreg[e + 1] + x3.z * wreg[e + 2] + x3.w * wreg[e + 3];
        }
        g_xw[(r0 + row + 0) * HID + j] = a0;
        g_xw[(r0 + row + 1) * HID + j] = a1;
        g_xw[(r0 + row + 2) * HID + j] = a2;
        g_xw[(r0 + row + 3) * HID + j] = a3;
    }
}

// ---------------------------------------------------------------------------
// Kernel 3: RNN scan chunk of tch steps. 1 batch/CTA, 128 thr. State carried
// through g_hst (fp32, exact) so each chunk continues bit-identically.
// ---------------------------------------------------------------------------
__global__ void __launch_bounds__(HID, 1) k_scan(const float* __restrict__ U,
                                                 int t0, int tch) {
    __shared__ __align__(16) float h[2][HID];
    int bb = blockIdx.x;
    int j  = threadIdx.x;

    unsigned long long u2[HID / 2];
    #pragma unroll
    for (int q = 0; q < HID / 2; q++)
        u2[q] = pack2(U[(2 * q) * HID + j], U[(2 * q + 1) * HID + j]);

    float h0 = (t0 == 0) ? 0.f : g_hst[bb * HID + j];
    h[0][j] = h0;
    __syncthreads();

    const float* xwp  = g_xw    + ((size_t)bb * TLEN + t0) * HID + j;
    __half*      outp = g_rnn_h + ((size_t)bb * TLEN + t0) * HID + j;
    float xw_cur = xwp[0];
    int buf = 0;
    float h_prev = 0.f;
    int   emit   = 0;

    #pragma unroll 1
    for (int t = 0; t < tch; t++) {
        float xw_next = (t < tch - 1) ? xwp[(t + 1) * HID] : 0.f;

        unsigned long long a[8];
        a[0] = pack2(xw_cur, 0.f);
        #pragma unroll
        for (int q = 1; q < 8; q++) a[q] = 0ull;

        const ulonglong2* hp = (const ulonglong2*)&h[buf][0];
        #pragma unroll
        for (int i = 0; i < 32; i++) {
            ulonglong2 hv = hp[i];
            fma2(a[(2 * i) & 7],     u2[2 * i],     hv.x);
            fma2(a[(2 * i + 1) & 7], u2[2 * i + 1], hv.y);
        }
        unsigned long long r0 = add2(a[0], a[1]);
        unsigned long long r1 = add2(a[2], a[3]);
        unsigned long long r2 = add2(a[4], a[5]);
        unsigned long long r3 = add2(a[6], a[7]);
        unsigned long long s  = add2(add2(r0, r1), add2(r2, r3));
        float zx, zy;
        unpack2(s, zx, zy);
        float z = zx + zy;

        float e = __expf(2.f * z);
        float hval = 1.f - __fdividef(2.f, e + 1.f);

        h[buf ^ 1][j] = hval;              // STS first: only thing the barrier gates
        __syncthreads();

        if (emit) outp[(t - 1) * HID] = __float2half(h_prev);
        h_prev = hval;
        emit = 1;
        buf ^= 1;
        xw_cur = xw_next;
    }
    outp[(tch - 1) * HID] = __float2half(h_prev);
    g_hst[bb * HID + j] = h_prev;          // state hand-off (exact fp32)
}

// ---------------------------------------------------------------------------
// Kernel 4: output GEMM chunk (timesteps [t0, t0+TL) of every batch).
// Templated on TL (segment length 32 or 64): A-tile 128 rows = (128/TL)
// batches' TL-row segments. B (v-tile 256) resident, 2 A-tiles per CTA
// double-buffered. Grid (40, BATCH*TL/256) per chunk.
// ---------------------------------------------------------------------------
#define SB_BYTES   65536                 // 256 rows x 256B (fp16)
#define SA_BYTES   32768                 // per stage: 128 rows x 256B
#define N_TILES    2
#define SM_TOTAL   (SB_BYTES + N_TILES * SA_BYTES)   // 128 KB

template<int TL>
__device__ __forceinline__ void gemm_load_a(uint32_t sAbuf, int bstart, int t0,
                                            int tid) {
    #pragma unroll
    for (int i = tid; i < 2048; i += 256) {       // 128 rows x 16 chunks
        int row = i >> 4, ch = i & 15;
        int gr = (bstart + row / TL) * TLEN + t0 + (row & (TL - 1));
        uint32_t dst = sAbuf + row * 256 + ((ch ^ (row & 7)) << 4);
        cp16(dst, g_rnn_h + (size_t)gr * HID + ch * 8);
    }
}

template<int TL>
__global__ void __launch_bounds__(256, 1) k_gemm(const float* __restrict__ bd,
                                                 float* __restrict__ out, int t0) {
    extern __shared__ char smem[];
    uint32_t sB  = smem_u32(smem);
    uint32_t sA0 = sB + SB_BYTES;

    int tid  = threadIdx.x;
    int wid  = tid >> 5;
    int lane = tid & 31;
    int v0   = blockIdx.x * 256;
    const int BPT = 128 / TL;               // batches per A-tile
    int bg   = blockIdx.y * (N_TILES * BPT);

    // ---- prologue: B (resident) + A0 in group 0; A1 in group 1 ----
    #pragma unroll
    for (int i = tid; i < 4096; i += 256) {       // B: 256 rows x 16 chunks
        int row = i >> 4, ch = i & 15;
        uint32_t dst = sB + row * 256 + ((ch ^ (row & 7)) << 4);
        cp16(dst, g_wdt_h + (size_t)(v0 + row) * HID + ch * 8);
    }
    gemm_load_a<TL>(sA0, bg, t0, tid);
    CP_COMMIT();
    gemm_load_a<TL>(sA0 + SA_BYTES, bg + BPT, t0, tid);
    CP_COMMIT();

    int wm = wid & 1;          // 2 warps over the 128 A rows (64 each)
    int wn = wid >> 1;         // 4 warps over v (64 each)
    int rA  = ((lane >> 3) & 1) * 8 + (lane & 7);
    int kcA = lane >> 4;
    int rB  = ((lane >> 4) & 1) * 8 + (lane & 7);
    int kcB = (lane >> 3) & 1;
    int lx  = lane & 7;

    #pragma unroll 1
    for (int it = 0; it < N_TILES; it++) {
        if (it == 0) { CP_WAIT(1); } else { CP_WAIT(0); }
        __syncthreads();

        uint32_t sAb = sA0 + it * SA_BYTES;
        int btile = bg + it * BPT;            // first batch of this A-tile

        float c[4][8][4];
        #pragma unroll
        for (int mb = 0; mb < 4; mb++)
            #pragma unroll
            for (int nb = 0; nb < 8; nb++)
                #pragma unroll
                for (int q = 0; q < 4; q++) c[mb][nb][q] = 0.f;

        uint32_t aBase = sAb + (uint32_t)(wm * 64 + rA) * 256;
        uint32_t bBase = sB  + (uint32_t)(wn * 64 + rB) * 256;
        #pragma unroll 1
        for (int ks = 0; ks < 8; ks++) {
            uint32_t a[4][4], b[4][4];
            int kA = (ks * 2 + kcA) ^ lx;
            int kB = (ks * 2 + kcB) ^ lx;
            #pragma unroll
            for (int mb = 0; mb < 4; mb++)
                ldsm_x4(a[mb], aBase + (uint32_t)(mb * 16) * 256 + (kA << 4));
            #pragma unroll
            for (int nb = 0; nb < 4; nb++)
                ldsm_x4(b[nb], bBase + (uint32_t)(nb * 16) * 256 + (kB << 4));
            #pragma unroll
            for (int mb = 0; mb < 4; mb++)
                #pragma unroll
                for (int nbi = 0; nbi < 8; nbi++)
                    mma16816(c[mb][nbi], a[mb],
                             b[nbi >> 1][(nbi & 1) * 2],
                             b[nbi >> 1][(nbi & 1) * 2 + 1]);
        }
        __syncthreads();

        // ---- epilogue: bias + store ----
        #pragma unroll
        for (int nbi = 0; nbi < 8; nbi++) {
            int col = v0 + wn * 64 + nbi * 8 + (lane & 3) * 2;
            if (col < VOCAB) {
                float b0 = bd[col], b1 = bd[col + 1];
                #pragma unroll
                for (int mb = 0; mb < 4; mb++) {
                    int lr0 = wm * 64 + mb * 16;          // local A row of c[..][0]
                    int r = (btile + lr0 / TL) * TLEN + t0 + (lr0 & (TL - 1))
                          + (lane >> 2);
                    float2 lo = make_float2(c[mb][nbi][0] + b0, c[mb][nbi][1] + b1);
                    float2 hi = make_float2(c[mb][nbi][2] + b0, c[mb][nbi][3] + b1);
                    *(float2*)(out + (size_t)r * VOCAB + col) = lo;
                    *(float2*)(out + (size_t)(r + 8) * VOCAB + col) = hi;
                }
            }
        }
    }
}

// ---------------------------------------------------------------------------
// Launch: chunks (32,64,64,64,32) — the round-10 passing structure — with
// the register-resident embed. s2 = wdt; s4 = embed rest; gemm alternates
// s3/s4, each gated only on its scan event (+ eWdt).
// ---------------------------------------------------------------------------
extern "C" void kernel_launch(void* const* d_in, const int* in_sizes, int n_in,
                              void* d_out, int out_size) {
    const void*  ids = d_in[0];
    const float* emb = (const float*)d_in[1];
    const float* W   = (const float*)d_in[2];
    const float* U   = (const float*)d_in[3];
    const float* b   = (const float*)d_in[4];
    const float* Wd  = (const float*)d_in[5];
    const float* bd  = (const float*)d_in[6];
    float* out = (float*)d_out;

    static cudaStream_t s2 = nullptr, s3 = nullptr, s4 = nullptr;
    static cudaEvent_t eD = nullptr, eFork = nullptr, eWdt = nullptr,
                       eEr1 = nullptr, eEr2 = nullptr,
                       eS[5] = {}, eG3 = nullptr, eG4 = nullptr;
    if (!s2) {
        cudaStreamCreateWithFlags(&s2, cudaStreamNonBlocking);
        cudaStreamCreateWithFlags(&s3, cudaStreamNonBlocking);
        cudaStreamCreateWithFlags(&s4, cudaStreamNonBlocking);
        cudaEventCreateWithFlags(&eD,    cudaEventDisableTiming);
        cudaEventCreateWithFlags(&eFork, cudaEventDisableTiming);
        cudaEventCreateWithFlags(&eWdt,  cudaEventDisableTiming);
        cudaEventCreateWithFlags(&eEr1,  cudaEventDisableTiming);
        cudaEventCreateWithFlags(&eEr2,  cudaEventDisableTiming);
        for (int i = 0; i < 5; i++) cudaEventCreateWithFlags(&eS[i], cudaEventDisableTiming);
        cudaEventCreateWithFlags(&eG3, cudaEventDisableTiming);
        cudaEventCreateWithFlags(&eG4, cudaEventDisableTiming);
        cudaFuncSetAttribute(k_gemm<64>, cudaFuncAttributeMaxDynamicSharedMemorySize, SM_TOTAL);
        cudaFuncSetAttribute(k_gemm<32>, cudaFuncAttributeMaxDynamicSharedMemorySize, SM_TOTAL);
    }

    // side stream s2: Wd transpose
    cudaEventRecord(eFork, 0);
    cudaStreamWaitEvent(s2, eFork, 0);
    k_wdt<<<dim3(VPAD / 32, HID / 32), dim3(32, 8), 0, s2>>>(Wd);
    cudaEventRecord(eWdt, s2);

    // main: detect + embed head (t < 32)
    k_detect<<<1, 256>>>((const unsigned int*)ids);
    cudaEventRecord(eD, 0);
    k_embed<<<BATCH, 256>>>(ids, emb, W, b, 0, 1);

    // s4: embed rest, split so scan chunks are never starved
    cudaStreamWaitEvent(s4, eD, 0);
    k_embed<<<BATCH * 2, 256, 0, s4>>>(ids, emb, W, b, 32, 2);    // t in [32,96)
    cudaEventRecord(eEr1, s4);
    k_embed<<<BATCH * 5, 256, 0, s4>>>(ids, emb, W, b, 96, 5);    // t in [96,256)
    cudaEventRecord(eEr2, s4);

    // main: scan chunks 32,64,64,64,32
    static const int t0s[5]  = {0, 32, 96, 160, 224};
    static const int tchs[5] = {32, 64, 64, 64, 32};
    k_scan<<<BATCH, HID>>>(U, t0s[0], tchs[0]);
    cudaEventRecord(eS[0], 0);
    cudaStreamWaitEvent(0, eEr1, 0);
    k_scan<<<BATCH, HID>>>(U, t0s[1], tchs[1]);
    cudaEventRecord(eS[1], 0);
    cudaStreamWaitEvent(0, eEr2, 0);
    for (int q = 2; q < 5; q++) {
        k_scan<<<BATCH, HID>>>(U, t0s[q], tchs[q]);
        cudaEventRecord(eS[q], 0);
    }

    // gemm chunks: q even on s3, q odd on s4; each gated on eWdt + its scan
    cudaStreamWaitEvent(s3, eWdt, 0);
    cudaStreamWaitEvent(s4, eWdt, 0);

    cudaStreamWaitEvent(s3, eS[0], 0);
    k_gemm<32><<<dim3(VPAD / 256, 4), 256, SM_TOTAL, s3>>>(bd, out, t0s[0]);
    cudaStreamWaitEvent(s4, eS[1], 0);
    k_gemm<64><<<dim3(VPAD / 256, 8), 256, SM_TOTAL, s4>>>(bd, out, t0s[1]);
    cudaStreamWaitEvent(s3, eS[2], 0);
    k_gemm<64><<<dim3(VPAD / 256, 8), 256, SM_TOTAL, s3>>>(bd, out, t0s[2]);
    cudaStreamWaitEvent(s4, eS[3], 0);
    k_gemm<64><<<dim3(VPAD / 256, 8), 256, SM_TOTAL, s4>>>(bd, out, t0s[3]);
    cudaStreamWaitEvent(s3, eS[4], 0);
    k_gemm<32><<<dim3(VPAD / 256, 4), 256, SM_TOTAL, s3>>>(bd, out, t0s[4]);

    cudaEventRecord(eG3, s3);
    cudaEventRecord(eG4, s4);
    cudaStreamWaitEvent(0, eG3, 0);
    cudaStreamWaitEvent(0, eG4, 0);
}